// round 1
// baseline (speedup 1.0000x reference)
#include <cuda_runtime.h>
#include <math.h>

#define D_MODEL 2048
#define NHEAD   16
#define HDIM    128
#define BATCH   2
#define SEQ     2048
#define MROWS   (BATCH*SEQ)   // 4096

// Scratch (device globals; no runtime allocation allowed)
__device__ float g_q[(size_t)BATCH*NHEAD*SEQ*HDIM];     // [B,H,L,128] roped+scaled
__device__ float g_k[(size_t)BATCH*NHEAD*SEQ*HDIM];     // [B,H,L,128] roped
__device__ float g_v[(size_t)BATCH*NHEAD*SEQ*HDIM];     // [B,H,L,128]
__device__ float g_attn[(size_t)BATCH*SEQ*D_MODEL];     // [B,L,H*128]

// ---------------------------------------------------------------------------
// Tiled fp32 GEMM:  C[M,N] = A[M,K] * B[N,K]^T + bias[N]
// BM=BN=64, BK=16, 256 threads, 4x4 per thread.
// MODE 0: write C row-major to C pointer (out projection -> d_out)
// MODE 1: QKV epilogue: scatter to g_q/g_k/g_v in [B,H,L,128] layout
// MODE 2: like MODE 0 but A is the internal g_attn buffer
// ---------------------------------------------------------------------------
template<int MODE>
__global__ __launch_bounds__(256, 2)
void gemm64(const float* __restrict__ A, const float* __restrict__ Bm,
            const float* __restrict__ bias, float* __restrict__ C,
            int M, int N, int K)
{
    __shared__ float As[16][68];
    __shared__ float Bs[16][68];

    const int tid  = threadIdx.x;
    const int ty   = tid >> 4;
    const int tx   = tid & 15;
    const int lrow = tid >> 2;          // 0..63
    const int lk   = (tid & 3) << 2;    // 0,4,8,12
    const int m0   = blockIdx.y << 6;
    const int n0   = blockIdx.x << 6;

    const float* Ap = (MODE == 2) ? g_attn : A;
    const float* Ag = Ap + (size_t)(m0 + lrow) * K + lk;
    const float* Bg = Bm + (size_t)(n0 + lrow) * K + lk;

    float acc[4][4];
    #pragma unroll
    for (int i = 0; i < 4; i++)
        #pragma unroll
        for (int j = 0; j < 4; j++) acc[i][j] = 0.f;

    for (int k0 = 0; k0 < K; k0 += 16) {
        float4 av = *(const float4*)(Ag + k0);
        float4 bv = *(const float4*)(Bg + k0);
        __syncthreads();
        As[lk+0][lrow] = av.x; As[lk+1][lrow] = av.y;
        As[lk+2][lrow] = av.z; As[lk+3][lrow] = av.w;
        Bs[lk+0][lrow] = bv.x; Bs[lk+1][lrow] = bv.y;
        Bs[lk+2][lrow] = bv.z; Bs[lk+3][lrow] = bv.w;
        __syncthreads();
        #pragma unroll
        for (int kk = 0; kk < 16; kk++) {
            float4 a4 = *(const float4*)&As[kk][ty << 2];
            float4 b4 = *(const float4*)&Bs[kk][tx << 2];
            acc[0][0] += a4.x*b4.x; acc[0][1] += a4.x*b4.y; acc[0][2] += a4.x*b4.z; acc[0][3] += a4.x*b4.w;
            acc[1][0] += a4.y*b4.x; acc[1][1] += a4.y*b4.y; acc[1][2] += a4.y*b4.z; acc[1][3] += a4.y*b4.w;
            acc[2][0] += a4.z*b4.x; acc[2][1] += a4.z*b4.y; acc[2][2] += a4.z*b4.z; acc[2][3] += a4.z*b4.w;
            acc[3][0] += a4.w*b4.x; acc[3][1] += a4.w*b4.y; acc[3][2] += a4.w*b4.z; acc[3][3] += a4.w*b4.w;
        }
    }

    const int n = n0 + (tx << 2);
    const float b0 = bias[n+0], b1 = bias[n+1], b2 = bias[n+2], b3 = bias[n+3];

    #pragma unroll
    for (int i = 0; i < 4; i++) {
        const int m = m0 + (ty << 2) + i;
        float4 r;
        r.x = acc[i][0] + b0;
        r.y = acc[i][1] + b1;
        r.z = acc[i][2] + b2;
        r.w = acc[i][3] + b3;
        if (MODE == 1) {
            const int which = n >> 11;          // 0=q 1=k 2=v
            const int h = (n >> 7) & 15;
            const int d = n & 127;
            const int b = m >> 11;
            const int l = m & (SEQ - 1);
            float* buf = (which == 0) ? g_q : (which == 1) ? g_k : g_v;
            *(float4*)&buf[(((size_t)(b*NHEAD + h))*SEQ + l)*HDIM + d] = r;
        } else {
            *(float4*)&C[(size_t)m * N + n] = r;
        }
    }
}

// ---------------------------------------------------------------------------
// RoPE (in place on g_q / g_k). One thread per (row, d in [0,64)).
// Double-precision angle + fmod range reduction (robust under fast-math).
// Q additionally scaled by 1/sqrt(128).
// ---------------------------------------------------------------------------
__global__ void rope_kernel()
{
    const int total = BATCH*NHEAD*SEQ*64;
    int idx = blockIdx.x * blockDim.x + threadIdx.x;
    if (idx >= total) return;
    const int d    = idx & 63;
    const int rowi = idx >> 6;              // (b*NHEAD+h)*SEQ + l
    const int l    = rowi & (SEQ - 1);

    double invf = exp2(-(double)d * (13.287712379549449 / 64.0)); // 10000^(-d/64)
    double t    = fmod((double)l * invf, 6.283185307179586476925286766559);
    float c = cosf((float)t);
    float s = sinf((float)t);

    const size_t base = (size_t)rowi * HDIM;
    const float qs = 0.08838834764831845f;  // 1/sqrt(128)

    float q1 = g_q[base + d], q2 = g_q[base + d + 64];
    g_q[base + d]      = (q1*c - q2*s) * qs;
    g_q[base + d + 64] = (q2*c + q1*s) * qs;

    float k1 = g_k[base + d], k2 = g_k[base + d + 64];
    g_k[base + d]      = k1*c - k2*s;
    g_k[base + d + 64] = k2*c + k1*s;
}

// ---------------------------------------------------------------------------
// Causal flash attention, fp32. BQ=BK=64. 256 threads.
// smem: Qst[128][64] (d-major), Kst[128][64] (d-major), Vs[64][128],
//       Ps[64][68], m/l/scale[64]
// S-phase: 16x16 threads, 4x4 each. PV-phase: thread t -> row t>>2,
// cols (t&3)*4 + 16*seg (interleaved -> conflict-free Vs reads).
// ---------------------------------------------------------------------------
__global__ __launch_bounds__(256, 1)
void attn_kernel()
{
    extern __shared__ float smbuf[];
    float* Qst   = smbuf;               // 128*64
    float* Kst   = Qst + 128*64;        // 128*64
    float* Vs    = Kst + 128*64;        // 64*128
    float* Ps    = Vs  + 64*128;        // 64*68
    float* m_sm  = Ps  + 64*68;         // 64
    float* l_sm  = m_sm + 64;           // 64
    float* sc_sm = l_sm + 64;           // 64

    const int tid = threadIdx.x;
    const int ty  = tid >> 4;
    const int tx  = tid & 15;
    const int qt  = blockIdx.x;
    const int h   = blockIdx.y;
    const int b   = blockIdx.z;
    const int bh  = b*NHEAD + h;
    const int q0  = qt << 6;

    const float* gq = g_q + (size_t)bh*SEQ*HDIM;
    const float* gk = g_k + (size_t)bh*SEQ*HDIM;
    const float* gv = g_v + (size_t)bh*SEQ*HDIM;

    // Load Q tile transposed: Qst[d][row]
    for (int t = tid; t < 64*32; t += 256) {
        const int row = t >> 5;
        const int d4  = (t & 31) << 2;
        float4 v = *(const float4*)&gq[(size_t)(q0 + row)*HDIM + d4];
        Qst[(d4+0)*64 + row] = v.x;
        Qst[(d4+1)*64 + row] = v.y;
        Qst[(d4+2)*64 + row] = v.z;
        Qst[(d4+3)*64 + row] = v.w;
    }
    if (tid < 64) { m_sm[tid] = -1e30f; l_sm[tid] = 0.f; }

    const int pr = tid >> 2;            // PV row (0..63)
    const int pc = (tid & 3) << 2;      // PV col base; cols pc + 16*seg + u
    float acc[32];
    #pragma unroll
    for (int i = 0; i < 32; i++) acc[i] = 0.f;

    for (int kt = 0; kt <= qt; kt++) {
        __syncthreads();  // previous PV readers done (and Q-load/init on iter 0)

        // Load K (transposed) and V tiles
        for (int t = tid; t < 64*32; t += 256) {
            const int row = t >> 5;
            const int d4  = (t & 31) << 2;
            float4 kv = *(const float4*)&gk[(size_t)((kt<<6) + row)*HDIM + d4];
            Kst[(d4+0)*64 + row] = kv.x;
            Kst[(d4+1)*64 + row] = kv.y;
            Kst[(d4+2)*64 + row] = kv.z;
            Kst[(d4+3)*64 + row] = kv.w;
            float4 vv = *(const float4*)&gv[(size_t)((kt<<6) + row)*HDIM + d4];
            *(float4*)&Vs[row*128 + d4] = vv;
        }
        __syncthreads();

        // ---- S = Q K^T (64x64), 4x4 per thread ----
        float s[4][4];
        #pragma unroll
        for (int i = 0; i < 4; i++)
            #pragma unroll
            for (int j = 0; j < 4; j++) s[i][j] = 0.f;

        #pragma unroll 4
        for (int k = 0; k < 128; k++) {
            float4 a  = *(const float4*)&Qst[k*64 + (ty << 2)];
            float4 bb = *(const float4*)&Kst[k*64 + (tx << 2)];
            s[0][0] += a.x*bb.x; s[0][1] += a.x*bb.y; s[0][2] += a.x*bb.z; s[0][3] += a.x*bb.w;
            s[1][0] += a.y*bb.x; s[1][1] += a.y*bb.y; s[1][2] += a.y*bb.z; s[1][3] += a.y*bb.w;
            s[2][0] += a.z*bb.x; s[2][1] += a.z*bb.y; s[2][2] += a.z*bb.z; s[2][3] += a.z*bb.w;
            s[3][0] += a.w*bb.x; s[3][1] += a.w*bb.y; s[3][2] += a.w*bb.z; s[3][3] += a.w*bb.w;
        }

        // Causal mask on the diagonal tile only
        if (kt == qt) {
            #pragma unroll
            for (int i = 0; i < 4; i++)
                #pragma unroll
                for (int j = 0; j < 4; j++)
                    if ((tx<<2) + j > (ty<<2) + i) s[i][j] = -1e30f;
        }

        // ---- Online softmax ----
        #pragma unroll
        for (int i = 0; i < 4; i++) {
            const int r = (ty << 2) + i;
            float rm = fmaxf(fmaxf(s[i][0], s[i][1]), fmaxf(s[i][2], s[i][3]));
            #pragma unroll
            for (int o = 8; o > 0; o >>= 1)
                rm = fmaxf(rm, __shfl_xor_sync(0xffffffffu, rm, o));
            const float mold = m_sm[r];
            const float mnew = fmaxf(mold, rm);
            float rs = 0.f;
            #pragma unroll
            for (int j = 0; j < 4; j++) {
                float p = __expf(s[i][j] - mnew);
                s[i][j] = p;
                rs += p;
            }
            #pragma unroll
            for (int o = 8; o > 0; o >>= 1)
                rs += __shfl_xor_sync(0xffffffffu, rs, o);
            __syncwarp();
            if (tx == 0) {
                const float sc = __expf(mold - mnew);
                l_sm[r]  = l_sm[r]*sc + rs;
                m_sm[r]  = mnew;
                sc_sm[r] = sc;
            }
            #pragma unroll
            for (int j = 0; j < 4; j++)
                Ps[r*68 + (tx<<2) + j] = s[i][j];
        }
        __syncthreads();

        // ---- O = O*scale + P V ----
        const float sc = sc_sm[pr];
        #pragma unroll
        for (int i = 0; i < 32; i++) acc[i] *= sc;
        for (int j = 0; j < 64; j++) {
            const float p = Ps[pr*68 + j];
            #pragma unroll
            for (int seg = 0; seg < 8; seg++) {
                float4 v = *(const float4*)&Vs[j*128 + pc + (seg<<4)];
                acc[seg*4+0] += p*v.x;
                acc[seg*4+1] += p*v.y;
                acc[seg*4+2] += p*v.z;
                acc[seg*4+3] += p*v.w;
            }
        }
    }

    // Epilogue: normalize and write [B, L, H, 128]
    const float inv = 1.f / l_sm[pr];
    float* outp = g_attn + (((size_t)(b*SEQ + q0 + pr))*NHEAD + h)*HDIM;
    #pragma unroll
    for (int seg = 0; seg < 8; seg++) {
        float4 r;
        r.x = acc[seg*4+0]*inv;
        r.y = acc[seg*4+1]*inv;
        r.z = acc[seg*4+2]*inv;
        r.w = acc[seg*4+3]*inv;
        *(float4*)&outp[pc + (seg<<4)] = r;
    }
}

// ---------------------------------------------------------------------------
extern "C" void kernel_launch(void* const* d_in, const int* in_sizes, int n_in,
                              void* d_out, int out_size)
{
    const float* query = (const float*)d_in[0];
    const float* W_qkv = (const float*)d_in[1];
    const float* b_qkv = (const float*)d_in[2];
    const float* W_out = (const float*)d_in[3];
    const float* b_out = (const float*)d_in[4];
    float* out = (float*)d_out;

    // Opt-in to >48KB dynamic smem for the attention kernel (no allocation).
    const int ATTN_SMEM = (128*64 + 128*64 + 64*128 + 64*68 + 3*64) * 4;
    cudaFuncSetAttribute(attn_kernel, cudaFuncAttributeMaxDynamicSharedMemorySize, ATTN_SMEM);

    dim3 blk(256);

    // 1) QKV projection -> g_q/g_k/g_v  ([B,H,L,128])
    gemm64<1><<<dim3(3*D_MODEL/64, MROWS/64), blk>>>(query, W_qkv, b_qkv, nullptr,
                                                     MROWS, 3*D_MODEL, D_MODEL);
    // 2) RoPE (q scaled by 1/sqrt(d))
    rope_kernel<<<(BATCH*NHEAD*SEQ*64)/256, 256>>>();

    // 3) Causal flash attention -> g_attn ([B,L,2048])
    attn_kernel<<<dim3(SEQ/64, NHEAD, BATCH), blk, ATTN_SMEM>>>();

    // 4) Output projection -> d_out
    gemm64<2><<<dim3(D_MODEL/64, MROWS/64), blk>>>(nullptr, W_out, b_out, out,
                                                   MROWS, D_MODEL, D_MODEL);
}

// round 3
// speedup vs baseline: 1.5800x; 1.5800x over previous
#include <cuda_runtime.h>
#include <cuda_bf16.h>
#include <math.h>
#include <stdint.h>

#define D_MODEL 2048
#define NHEAD   16
#define HDIM    128
#define BATCH   2
#define SEQ     2048
#define MROWS   (BATCH*SEQ)   // 4096

// ---------------- device scratch (no runtime allocation) ----------------
__device__ float g_q[(size_t)BATCH*NHEAD*SEQ*HDIM];     // [B,H,L,128] roped+scaled
__device__ float g_k[(size_t)BATCH*NHEAD*SEQ*HDIM];     // [B,H,L,128] roped
__device__ float g_v[(size_t)BATCH*NHEAD*SEQ*HDIM];     // [B,H,L,128]
__device__ float g_attn[(size_t)BATCH*SEQ*D_MODEL];     // [B,L,H*128]

__device__ __nv_bfloat16 g_qh[(size_t)MROWS*D_MODEL];       // query hi/lo
__device__ __nv_bfloat16 g_ql[(size_t)MROWS*D_MODEL];
__device__ __nv_bfloat16 g_wh[(size_t)3*D_MODEL*D_MODEL];   // W_qkv hi/lo
__device__ __nv_bfloat16 g_wl[(size_t)3*D_MODEL*D_MODEL];
__device__ __nv_bfloat16 g_oh[(size_t)D_MODEL*D_MODEL];     // W_out hi/lo
__device__ __nv_bfloat16 g_ol[(size_t)D_MODEL*D_MODEL];
__device__ __nv_bfloat16 g_ah[(size_t)MROWS*D_MODEL];       // attn-out hi/lo
__device__ __nv_bfloat16 g_al[(size_t)MROWS*D_MODEL];

// ---------------- helpers ----------------
__device__ __forceinline__ uint32_t smem_u32(const void* p) {
    uint32_t a;
    asm("{ .reg .u64 t; cvta.to.shared.u64 t, %1; cvt.u32.u64 %0, t; }" : "=r"(a) : "l"(p));
    return a;
}
#define SWZ(o) ((o) ^ (((o) >> 3) & 0x70))

__device__ __forceinline__ void ldsm4(uint32_t addr, uint32_t* r) {
    asm volatile("ldmatrix.sync.aligned.m8n8.x4.shared.b16 {%0,%1,%2,%3}, [%4];"
                 : "=r"(r[0]), "=r"(r[1]), "=r"(r[2]), "=r"(r[3]) : "r"(addr));
}
__device__ __forceinline__ void mma16816(float* c, const uint32_t* a, const uint32_t* b) {
    asm volatile(
        "mma.sync.aligned.m16n8k16.row.col.f32.bf16.bf16.f32 "
        "{%0,%1,%2,%3}, {%4,%5,%6,%7}, {%8,%9}, {%0,%1,%2,%3};"
        : "+f"(c[0]), "+f"(c[1]), "+f"(c[2]), "+f"(c[3])
        : "r"(a[0]), "r"(a[1]), "r"(a[2]), "r"(a[3]), "r"(b[0]), "r"(b[1]));
}

// ---------------------------------------------------------------------------
// fp32 -> bf16 hi/lo split (3xBF16 decomposition)
// ---------------------------------------------------------------------------
__global__ void split_kernel(const float* __restrict__ x,
                             __nv_bfloat16* __restrict__ hi,
                             __nv_bfloat16* __restrict__ lo, int n)
{
    int i = (blockIdx.x * 256 + threadIdx.x) * 4;
    if (i >= n) return;
    float4 v = *(const float4*)(x + i);
    float a[4] = {v.x, v.y, v.z, v.w};
    uint32_t ph[2], pl[2];
    #pragma unroll
    for (int p = 0; p < 2; p++) {
        __nv_bfloat16 h0 = __float2bfloat16(a[2*p+0]);
        __nv_bfloat16 h1 = __float2bfloat16(a[2*p+1]);
        __nv_bfloat16 l0 = __float2bfloat16(a[2*p+0] - __bfloat162float(h0));
        __nv_bfloat16 l1 = __float2bfloat16(a[2*p+1] - __bfloat162float(h1));
        ph[p] = ((uint32_t)__bfloat16_as_ushort(h1) << 16) | __bfloat16_as_ushort(h0);
        pl[p] = ((uint32_t)__bfloat16_as_ushort(l1) << 16) | __bfloat16_as_ushort(l0);
    }
    *(uint2*)(hi + i) = make_uint2(ph[0], ph[1]);
    *(uint2*)(lo + i) = make_uint2(pl[0], pl[1]);
}

// ---------------------------------------------------------------------------
// HMMA GEMM:  C[M,N] = Ah*Bh^T + Ah*Bl^T + Al*Bh^T + bias   (fp32 accum)
// CTA 128x128, 8 warps (64x32 each), K-chunks of 64 bf16, double-buffered
// SW128-swizzled smem. A row-major [M,K], B row-major [N,K].
// MODE 0: write C row-major.  MODE 1: scatter to g_q/g_k/g_v [B,H,L,128].
// ---------------------------------------------------------------------------
__device__ __forceinline__ void load_tiles(
    const __nv_bfloat16* __restrict__ a0, const __nv_bfloat16* __restrict__ a1,
    const __nv_bfloat16* __restrict__ b0, const __nv_bfloat16* __restrict__ b1,
    int K, uint32_t dst)
{
    const __nv_bfloat16* s[4] = {a0, a1, b0, b1};
    #pragma unroll
    for (int t = 0; t < 4; t++) {
        uint32_t d = dst + t * 16384;
        const __nv_bfloat16* p = s[t];
        #pragma unroll
        for (int it = 0; it < 4; it++) {
            int i = threadIdx.x + it * 256;
            int r = i >> 3, c = i & 7;
            uint4 v = *(const uint4*)(p + (size_t)r * K + c * 8);
            uint32_t off = d + SWZ(r * 128 + c * 16);
            asm volatile("st.shared.v4.b32 [%0], {%1,%2,%3,%4};"
                         :: "r"(off), "r"(v.x), "r"(v.y), "r"(v.z), "r"(v.w));
        }
    }
}

template<int MODE>
__global__ __launch_bounds__(256, 1)
void tc_gemm(const __nv_bfloat16* __restrict__ Ah, const __nv_bfloat16* __restrict__ Al,
             const __nv_bfloat16* __restrict__ Bh, const __nv_bfloat16* __restrict__ Bl,
             const float* __restrict__ bias, float* __restrict__ C, int N, int K)
{
    extern __shared__ char smem[];
    const uint32_t bufs = (smem_u32(smem) + 1023) & ~1023u;

    const int tid  = threadIdx.x;
    const int lane = tid & 31;
    const int wid  = tid >> 5;
    const int wr   = wid >> 2;      // 0..1 : 64-row slice
    const int wc   = wid & 3;       // 0..3 : 32-col slice
    const int m0   = blockIdx.y << 7;
    const int n0   = blockIdx.x << 7;
    const int KCHUNKS = K >> 6;

    const __nv_bfloat16* Ahp = Ah + (size_t)m0 * K;
    const __nv_bfloat16* Alp = Al + (size_t)m0 * K;
    const __nv_bfloat16* Bhp = Bh + (size_t)n0 * K;
    const __nv_bfloat16* Blp = Bl + (size_t)n0 * K;

    float acc[4][4][4];
    #pragma unroll
    for (int i = 0; i < 4; i++)
        #pragma unroll
        for (int j = 0; j < 4; j++)
            #pragma unroll
            for (int r = 0; r < 4; r++) acc[i][j][r] = 0.f;

    // ldmatrix lane geometry (shared swizzle term for A and B)
    const uint32_t sw   = (lane & 7) << 4;
    const int      arow = lane & 15;                       // A: rows r0..r0+15
    const uint32_t adk  = (lane >> 4) << 4;                // A: +16B for k8..15
    const int      brow = (lane & 7) + ((lane >> 4) << 3); // B: n rows
    const uint32_t bdk  = ((lane >> 3) & 1) << 4;          // B: +16B for k8..15

    // per-warp row base offsets inside tiles
    uint32_t aro[4], bro[2];
    #pragma unroll
    for (int mt = 0; mt < 4; mt++) aro[mt] = (uint32_t)(wr*64 + mt*16 + arow) * 128;
    #pragma unroll
    for (int np = 0; np < 2; np++) bro[np] = (uint32_t)(wc*32 + np*16 + brow) * 128;

    // prologue: chunk 0 -> buffer 0
    load_tiles(Ahp, Alp, Bhp, Blp, K, bufs);
    __syncthreads();

    for (int c = 0; c < KCHUNKS; c++) {
        const uint32_t base = bufs + (c & 1) * 65536;
        if (c + 1 < KCHUNKS) {
            const int k64 = (c + 1) << 6;
            load_tiles(Ahp + k64, Alp + k64, Bhp + k64, Blp + k64, K,
                       bufs + ((c + 1) & 1) * 65536);
        }
        const uint32_t bAh = base, bAl = base + 16384, bBh = base + 32768, bBl = base + 49152;

        #pragma unroll
        for (int ks = 0; ks < 4; ks++) {
            const uint32_t kb  = (uint32_t)ks * 32;
            const uint32_t kcA = (kb + adk) ^ sw;
            const uint32_t kcB = (kb + bdk) ^ sw;

            uint32_t ah[4][4], al[4][4], bhx[2][4], blx[2][4];
            #pragma unroll
            for (int mt = 0; mt < 4; mt++) {
                ldsm4(bAh + aro[mt] + kcA, ah[mt]);
                ldsm4(bAl + aro[mt] + kcA, al[mt]);
            }
            #pragma unroll
            for (int np = 0; np < 2; np++) {
                ldsm4(bBh + bro[np] + kcB, bhx[np]);
                ldsm4(bBl + bro[np] + kcB, blx[np]);
            }
            #pragma unroll
            for (int mt = 0; mt < 4; mt++)
                #pragma unroll
                for (int nt = 0; nt < 4; nt++) {
                    const uint32_t* bh2 = &bhx[nt >> 1][(nt & 1) * 2];
                    const uint32_t* bl2 = &blx[nt >> 1][(nt & 1) * 2];
                    mma16816(acc[mt][nt], ah[mt], bh2);
                    mma16816(acc[mt][nt], ah[mt], bl2);
                    mma16816(acc[mt][nt], al[mt], bh2);
                }
        }
        __syncthreads();
    }

    // ---------------- epilogue ----------------
    const int which = n0 >> 11;            // MODE 1 only
    const int h     = (n0 >> 7) & 15;
    float* qkvbase  = (which == 0) ? g_q : (which == 1) ? g_k : g_v;

    #pragma unroll
    for (int mt = 0; mt < 4; mt++) {
        const int mrow = m0 + wr*64 + mt*16 + (lane >> 2);
        #pragma unroll
        for (int nt = 0; nt < 4; nt++) {
            const int cl = wc*32 + nt*8 + (lane & 3)*2;    // tile-local col
            const int cg = n0 + cl;                        // global col
            const float bx = bias[cg], by = bias[cg + 1];
            float2 v0 = make_float2(acc[mt][nt][0] + bx, acc[mt][nt][1] + by);
            float2 v1 = make_float2(acc[mt][nt][2] + bx, acc[mt][nt][3] + by);
            if (MODE == 1) {
                const int b0r = mrow >> 11, l0r = mrow & (SEQ - 1);
                float* p0 = qkvbase + (((size_t)(b0r*NHEAD + h))*SEQ + l0r)*HDIM + cl;
                const int m1 = mrow + 8;
                const int b1r = m1 >> 11, l1r = m1 & (SEQ - 1);
                float* p1 = qkvbase + (((size_t)(b1r*NHEAD + h))*SEQ + l1r)*HDIM + cl;
                *(float2*)p0 = v0;
                *(float2*)p1 = v1;
            } else {
                *(float2*)&C[(size_t)mrow * N + cg]       = v0;
                *(float2*)&C[(size_t)(mrow + 8) * N + cg] = v1;
            }
        }
    }
}

// ---------------------------------------------------------------------------
// RoPE (in place on g_q / g_k), double-precision range reduction.
// ---------------------------------------------------------------------------
__global__ void rope_kernel()
{
    const int total = BATCH*NHEAD*SEQ*64;
    int idx = blockIdx.x * blockDim.x + threadIdx.x;
    if (idx >= total) return;
    const int d    = idx & 63;
    const int rowi = idx >> 6;
    const int l    = rowi & (SEQ - 1);

    double invf = exp2(-(double)d * (13.287712379549449 / 64.0)); // 10000^(-d/64)
    double t    = fmod((double)l * invf, 6.283185307179586476925286766559);
    float c = cosf((float)t);
    float s = sinf((float)t);

    const size_t base = (size_t)rowi * HDIM;
    const float qs = 0.08838834764831845f;  // 1/sqrt(128)

    float q1 = g_q[base + d], q2 = g_q[base + d + 64];
    g_q[base + d]      = (q1*c - q2*s) * qs;
    g_q[base + d + 64] = (q2*c + q1*s) * qs;

    float k1 = g_k[base + d], k2 = g_k[base + d + 64];
    g_k[base + d]      = k1*c - k2*s;
    g_k[base + d + 64] = k2*c + k1*s;
}

// ---------------------------------------------------------------------------
// Causal flash attention, fp32 (unchanged, proven).
// ---------------------------------------------------------------------------
__global__ __launch_bounds__(256, 1)
void attn_kernel()
{
    extern __shared__ float smbuf[];
    float* Qst   = smbuf;               // 128*64
    float* Kst   = Qst + 128*64;        // 128*64
    float* Vs    = Kst + 128*64;        // 64*128
    float* Ps    = Vs  + 64*128;        // 64*68
    float* m_sm  = Ps  + 64*68;         // 64
    float* l_sm  = m_sm + 64;           // 64
    float* sc_sm = l_sm + 64;           // 64

    const int tid = threadIdx.x;
    const int ty  = tid >> 4;
    const int tx  = tid & 15;
    const int qt  = blockIdx.x;
    const int h   = blockIdx.y;
    const int b   = blockIdx.z;
    const int bh  = b*NHEAD + h;
    const int q0  = qt << 6;

    const float* gq = g_q + (size_t)bh*SEQ*HDIM;
    const float* gk = g_k + (size_t)bh*SEQ*HDIM;
    const float* gv = g_v + (size_t)bh*SEQ*HDIM;

    for (int t = tid; t < 64*32; t += 256) {
        const int row = t >> 5;
        const int d4  = (t & 31) << 2;
        float4 v = *(const float4*)&gq[(size_t)(q0 + row)*HDIM + d4];
        Qst[(d4+0)*64 + row] = v.x;
        Qst[(d4+1)*64 + row] = v.y;
        Qst[(d4+2)*64 + row] = v.z;
        Qst[(d4+3)*64 + row] = v.w;
    }
    if (tid < 64) { m_sm[tid] = -1e30f; l_sm[tid] = 0.f; }

    const int pr = tid >> 2;
    const int pc = (tid & 3) << 2;
    float acc[32];
    #pragma unroll
    for (int i = 0; i < 32; i++) acc[i] = 0.f;

    for (int kt = 0; kt <= qt; kt++) {
        __syncthreads();

        for (int t = tid; t < 64*32; t += 256) {
            const int row = t >> 5;
            const int d4  = (t & 31) << 2;
            float4 kv = *(const float4*)&gk[(size_t)((kt<<6) + row)*HDIM + d4];
            Kst[(d4+0)*64 + row] = kv.x;
            Kst[(d4+1)*64 + row] = kv.y;
            Kst[(d4+2)*64 + row] = kv.z;
            Kst[(d4+3)*64 + row] = kv.w;
            float4 vv = *(const float4*)&gv[(size_t)((kt<<6) + row)*HDIM + d4];
            *(float4*)&Vs[row*128 + d4] = vv;
        }
        __syncthreads();

        float s[4][4];
        #pragma unroll
        for (int i = 0; i < 4; i++)
            #pragma unroll
            for (int j = 0; j < 4; j++) s[i][j] = 0.f;

        #pragma unroll 4
        for (int k = 0; k < 128; k++) {
            float4 a  = *(const float4*)&Qst[k*64 + (ty << 2)];
            float4 bb = *(const float4*)&Kst[k*64 + (tx << 2)];
            s[0][0] += a.x*bb.x; s[0][1] += a.x*bb.y; s[0][2] += a.x*bb.z; s[0][3] += a.x*bb.w;
            s[1][0] += a.y*bb.x; s[1][1] += a.y*bb.y; s[1][2] += a.y*bb.z; s[1][3] += a.y*bb.w;
            s[2][0] += a.z*bb.x; s[2][1] += a.z*bb.y; s[2][2] += a.z*bb.z; s[2][3] += a.z*bb.w;
            s[3][0] += a.w*bb.x; s[3][1] += a.w*bb.y; s[3][2] += a.w*bb.z; s[3][3] += a.w*bb.w;
        }

        if (kt == qt) {
            #pragma unroll
            for (int i = 0; i < 4; i++)
                #pragma unroll
                for (int j = 0; j < 4; j++)
                    if ((tx<<2) + j > (ty<<2) + i) s[i][j] = -1e30f;
        }

        #pragma unroll
        for (int i = 0; i < 4; i++) {
            const int r = (ty << 2) + i;
            float rm = fmaxf(fmaxf(s[i][0], s[i][1]), fmaxf(s[i][2], s[i][3]));
            #pragma unroll
            for (int o = 8; o > 0; o >>= 1)
                rm = fmaxf(rm, __shfl_xor_sync(0xffffffffu, rm, o));
            const float mold = m_sm[r];
            const float mnew = fmaxf(mold, rm);
            float rs = 0.f;
            #pragma unroll
            for (int j = 0; j < 4; j++) {
                float p = __expf(s[i][j] - mnew);
                s[i][j] = p;
                rs += p;
            }
            #pragma unroll
            for (int o = 8; o > 0; o >>= 1)
                rs += __shfl_xor_sync(0xffffffffu, rs, o);
            __syncwarp();
            if (tx == 0) {
                const float sc = __expf(mold - mnew);
                l_sm[r]  = l_sm[r]*sc + rs;
                m_sm[r]  = mnew;
                sc_sm[r] = sc;
            }
            #pragma unroll
            for (int j = 0; j < 4; j++)
                Ps[r*68 + (tx<<2) + j] = s[i][j];
        }
        __syncthreads();

        const float sc = sc_sm[pr];
        #pragma unroll
        for (int i = 0; i < 32; i++) acc[i] *= sc;
        for (int j = 0; j < 64; j++) {
            const float p = Ps[pr*68 + j];
            #pragma unroll
            for (int seg = 0; seg < 8; seg++) {
                float4 v = *(const float4*)&Vs[j*128 + pc + (seg<<4)];
                acc[seg*4+0] += p*v.x;
                acc[seg*4+1] += p*v.y;
                acc[seg*4+2] += p*v.z;
                acc[seg*4+3] += p*v.w;
            }
        }
    }

    const float inv = 1.f / l_sm[pr];
    float* outp = g_attn + (((size_t)(b*SEQ + q0 + pr))*NHEAD + h)*HDIM;
    #pragma unroll
    for (int seg = 0; seg < 8; seg++) {
        float4 r;
        r.x = acc[seg*4+0]*inv;
        r.y = acc[seg*4+1]*inv;
        r.z = acc[seg*4+2]*inv;
        r.w = acc[seg*4+3]*inv;
        *(float4*)&outp[pc + (seg<<4)] = r;
    }
}

// ---------------------------------------------------------------------------
extern "C" void kernel_launch(void* const* d_in, const int* in_sizes, int n_in,
                              void* d_out, int out_size)
{
    const float* query = (const float*)d_in[0];
    const float* W_qkv = (const float*)d_in[1];
    const float* b_qkv = (const float*)d_in[2];
    const float* W_out = (const float*)d_in[3];
    const float* b_out = (const float*)d_in[4];
    float* out = (float*)d_out;

    void *p_qh, *p_ql, *p_wh, *p_wl, *p_oh, *p_ol, *p_ah, *p_al, *p_attn;
    cudaGetSymbolAddress(&p_qh, g_qh);  cudaGetSymbolAddress(&p_ql, g_ql);
    cudaGetSymbolAddress(&p_wh, g_wh);  cudaGetSymbolAddress(&p_wl, g_wl);
    cudaGetSymbolAddress(&p_oh, g_oh);  cudaGetSymbolAddress(&p_ol, g_ol);
    cudaGetSymbolAddress(&p_ah, g_ah);  cudaGetSymbolAddress(&p_al, g_al);
    cudaGetSymbolAddress(&p_attn, g_attn);

    const int ATTN_SMEM = (128*64 + 128*64 + 64*128 + 64*68 + 3*64) * 4;
    cudaFuncSetAttribute(attn_kernel, cudaFuncAttributeMaxDynamicSharedMemorySize, ATTN_SMEM);
    const int GEMM_SMEM = 1024 + 2*65536;
    cudaFuncSetAttribute(tc_gemm<0>, cudaFuncAttributeMaxDynamicSharedMemorySize, GEMM_SMEM);
    cudaFuncSetAttribute(tc_gemm<1>, cudaFuncAttributeMaxDynamicSharedMemorySize, GEMM_SMEM);

    // 1) split inputs into bf16 hi/lo
    {
        int n;
        n = MROWS*D_MODEL;
        split_kernel<<<n/1024, 256>>>(query, (__nv_bfloat16*)p_qh, (__nv_bfloat16*)p_ql, n);
        n = 3*D_MODEL*D_MODEL;
        split_kernel<<<n/1024, 256>>>(W_qkv, (__nv_bfloat16*)p_wh, (__nv_bfloat16*)p_wl, n);
        n = D_MODEL*D_MODEL;
        split_kernel<<<n/1024, 256>>>(W_out, (__nv_bfloat16*)p_oh, (__nv_bfloat16*)p_ol, n);
    }

    // 2) QKV projection (HMMA) -> g_q/g_k/g_v [B,H,L,128]
    tc_gemm<1><<<dim3(3*D_MODEL/128, MROWS/128), 256, GEMM_SMEM>>>(
        (const __nv_bfloat16*)p_qh, (const __nv_bfloat16*)p_ql,
        (const __nv_bfloat16*)p_wh, (const __nv_bfloat16*)p_wl,
        b_qkv, nullptr, 3*D_MODEL, D_MODEL);

    // 3) RoPE (q scaled by 1/sqrt(d))
    rope_kernel<<<(BATCH*NHEAD*SEQ*64)/256, 256>>>();

    // 4) Causal flash attention -> g_attn [B,L,2048]
    attn_kernel<<<dim3(SEQ/64, NHEAD, BATCH), 256, ATTN_SMEM>>>();

    // 5) split attention output, then output projection (HMMA) -> d_out
    {
        int n = MROWS*D_MODEL;
        split_kernel<<<n/1024, 256>>>((const float*)p_attn,
                                      (__nv_bfloat16*)p_ah, (__nv_bfloat16*)p_al, n);
    }
    tc_gemm<0><<<dim3(D_MODEL/128, MROWS/128), 256, GEMM_SMEM>>>(
        (const __nv_bfloat16*)p_ah, (const __nv_bfloat16*)p_al,
        (const __nv_bfloat16*)p_oh, (const __nv_bfloat16*)p_ol,
        b_out, out, D_MODEL, D_MODEL);
}

// round 4
// speedup vs baseline: 3.3456x; 2.1174x over previous
#include <cuda_runtime.h>
#include <cuda_bf16.h>
#include <math.h>
#include <stdint.h>

#define D_MODEL 2048
#define NHEAD   16
#define HDIM    128
#define BATCH   2
#define SEQ     2048
#define MROWS   (BATCH*SEQ)   // 4096

// ---------------- device scratch (no runtime allocation) ----------------
__device__ float g_q[(size_t)BATCH*NHEAD*SEQ*HDIM];     // fp32 pre-rope Q
__device__ float g_k[(size_t)BATCH*NHEAD*SEQ*HDIM];     // fp32 pre-rope K

__device__ __nv_bfloat16 g_qbh[(size_t)BATCH*NHEAD*SEQ*HDIM];  // roped+scaled Q hi/lo
__device__ __nv_bfloat16 g_qbl[(size_t)BATCH*NHEAD*SEQ*HDIM];
__device__ __nv_bfloat16 g_kbh[(size_t)BATCH*NHEAD*SEQ*HDIM];  // roped K hi/lo
__device__ __nv_bfloat16 g_kbl[(size_t)BATCH*NHEAD*SEQ*HDIM];
__device__ __nv_bfloat16 g_vbh[(size_t)BATCH*NHEAD*SEQ*HDIM];  // V hi/lo
__device__ __nv_bfloat16 g_vbl[(size_t)BATCH*NHEAD*SEQ*HDIM];

__device__ __nv_bfloat16 g_qh[(size_t)MROWS*D_MODEL];       // query hi/lo (GEMM A)
__device__ __nv_bfloat16 g_ql[(size_t)MROWS*D_MODEL];
__device__ __nv_bfloat16 g_wh[(size_t)3*D_MODEL*D_MODEL];   // W_qkv hi/lo
__device__ __nv_bfloat16 g_wl[(size_t)3*D_MODEL*D_MODEL];
__device__ __nv_bfloat16 g_oh[(size_t)D_MODEL*D_MODEL];     // W_out hi/lo
__device__ __nv_bfloat16 g_ol[(size_t)D_MODEL*D_MODEL];
__device__ __nv_bfloat16 g_ah[(size_t)MROWS*D_MODEL];       // attn-out hi/lo
__device__ __nv_bfloat16 g_al[(size_t)MROWS*D_MODEL];

// ---------------- helpers ----------------
__device__ __forceinline__ uint32_t smem_u32(const void* p) {
    uint32_t a;
    asm("{ .reg .u64 t; cvta.to.shared.u64 t, %1; cvt.u32.u64 %0, t; }" : "=r"(a) : "l"(p));
    return a;
}
#define SWZ(o) ((o) ^ (((o) >> 3) & 0x70))

__device__ __forceinline__ void ldsm4(uint32_t addr, uint32_t* r) {
    asm volatile("ldmatrix.sync.aligned.m8n8.x4.shared.b16 {%0,%1,%2,%3}, [%4];"
                 : "=r"(r[0]), "=r"(r[1]), "=r"(r[2]), "=r"(r[3]) : "r"(addr));
}
__device__ __forceinline__ void ldsm4t(uint32_t addr, uint32_t* r) {
    asm volatile("ldmatrix.sync.aligned.m8n8.x4.trans.shared.b16 {%0,%1,%2,%3}, [%4];"
                 : "=r"(r[0]), "=r"(r[1]), "=r"(r[2]), "=r"(r[3]) : "r"(addr));
}
__device__ __forceinline__ void mma16816(float* c, const uint32_t* a, const uint32_t* b) {
    asm volatile(
        "mma.sync.aligned.m16n8k16.row.col.f32.bf16.bf16.f32 "
        "{%0,%1,%2,%3}, {%4,%5,%6,%7}, {%8,%9}, {%0,%1,%2,%3};"
        : "+f"(c[0]), "+f"(c[1]), "+f"(c[2]), "+f"(c[3])
        : "r"(a[0]), "r"(a[1]), "r"(a[2]), "r"(a[3]), "r"(b[0]), "r"(b[1]));
}
#define CP16(dst, src) \
    asm volatile("cp.async.cg.shared.global [%0], [%1], 16;" :: "r"(dst), "l"(src))
#define CP_COMMIT() asm volatile("cp.async.commit_group;" ::: "memory")
#define CP_WAIT0()  asm volatile("cp.async.wait_group 0;" ::: "memory")

// split pair of fp32 into packed bf16x2 hi and lo (residual)
__device__ __forceinline__ void split2(float x, float y, uint32_t& hi, uint32_t& lo) {
    __nv_bfloat16 hx = __float2bfloat16(x), hy = __float2bfloat16(y);
    float rx = x - __bfloat162float(hx), ry = y - __bfloat162float(hy);
    __nv_bfloat16 lx = __float2bfloat16(rx), ly = __float2bfloat16(ry);
    hi = ((uint32_t)__bfloat16_as_ushort(hy) << 16) | __bfloat16_as_ushort(hx);
    lo = ((uint32_t)__bfloat16_as_ushort(ly) << 16) | __bfloat16_as_ushort(lx);
}

// ---------------------------------------------------------------------------
// fp32 -> bf16 hi/lo split
// ---------------------------------------------------------------------------
__global__ void split_kernel(const float* __restrict__ x,
                             __nv_bfloat16* __restrict__ hi,
                             __nv_bfloat16* __restrict__ lo, int n)
{
    int i = (blockIdx.x * 256 + threadIdx.x) * 4;
    if (i >= n) return;
    float4 v = *(const float4*)(x + i);
    uint32_t h0, l0, h1, l1;
    split2(v.x, v.y, h0, l0);
    split2(v.z, v.w, h1, l1);
    *(uint2*)(hi + i) = make_uint2(h0, h1);
    *(uint2*)(lo + i) = make_uint2(l0, l1);
}

// ---------------------------------------------------------------------------
// HMMA GEMM:  C = Ah*Bh^T + Ah*Bl^T + Al*Bh^T + bias   (fp32 accum)
// CTA 128x128, 8 warps, K-chunks of 64 bf16, double-buffered SW128 smem.
// MODE 0: write C fp32 row-major.
// MODE 1: QKV: q,k -> fp32 [B,H,L,128]; v -> bf16 hi/lo [B,H,L,128].
// ---------------------------------------------------------------------------
__device__ __forceinline__ void load_tiles(
    const __nv_bfloat16* __restrict__ a0, const __nv_bfloat16* __restrict__ a1,
    const __nv_bfloat16* __restrict__ b0, const __nv_bfloat16* __restrict__ b1,
    int K, uint32_t dst)
{
    const __nv_bfloat16* s[4] = {a0, a1, b0, b1};
    #pragma unroll
    for (int t = 0; t < 4; t++) {
        uint32_t d = dst + t * 16384;
        const __nv_bfloat16* p = s[t];
        #pragma unroll
        for (int it = 0; it < 4; it++) {
            int i = threadIdx.x + it * 256;
            int r = i >> 3, c = i & 7;
            uint4 v = *(const uint4*)(p + (size_t)r * K + c * 8);
            uint32_t off = d + SWZ(r * 128 + c * 16);
            asm volatile("st.shared.v4.b32 [%0], {%1,%2,%3,%4};"
                         :: "r"(off), "r"(v.x), "r"(v.y), "r"(v.z), "r"(v.w));
        }
    }
}

template<int MODE>
__global__ __launch_bounds__(256, 1)
void tc_gemm(const __nv_bfloat16* __restrict__ Ah, const __nv_bfloat16* __restrict__ Al,
             const __nv_bfloat16* __restrict__ Bh, const __nv_bfloat16* __restrict__ Bl,
             const float* __restrict__ bias, float* __restrict__ C, int N, int K)
{
    extern __shared__ char smem[];
    const uint32_t bufs = (smem_u32(smem) + 1023) & ~1023u;

    const int tid  = threadIdx.x;
    const int lane = tid & 31;
    const int wid  = tid >> 5;
    const int wr   = wid >> 2;
    const int wc   = wid & 3;
    const int m0   = blockIdx.y << 7;
    const int n0   = blockIdx.x << 7;
    const int KCHUNKS = K >> 6;

    const __nv_bfloat16* Ahp = Ah + (size_t)m0 * K;
    const __nv_bfloat16* Alp = Al + (size_t)m0 * K;
    const __nv_bfloat16* Bhp = Bh + (size_t)n0 * K;
    const __nv_bfloat16* Blp = Bl + (size_t)n0 * K;

    float acc[4][4][4];
    #pragma unroll
    for (int i = 0; i < 4; i++)
        #pragma unroll
        for (int j = 0; j < 4; j++)
            #pragma unroll
            for (int r = 0; r < 4; r++) acc[i][j][r] = 0.f;

    const uint32_t sw   = (lane & 7) << 4;
    const int      arow = lane & 15;
    const uint32_t adk  = (lane >> 4) << 4;
    const int      brow = (lane & 7) + ((lane >> 4) << 3);
    const uint32_t bdk  = ((lane >> 3) & 1) << 4;

    uint32_t aro[4], bro[2];
    #pragma unroll
    for (int mt = 0; mt < 4; mt++) aro[mt] = (uint32_t)(wr*64 + mt*16 + arow) * 128;
    #pragma unroll
    for (int np = 0; np < 2; np++) bro[np] = (uint32_t)(wc*32 + np*16 + brow) * 128;

    load_tiles(Ahp, Alp, Bhp, Blp, K, bufs);
    __syncthreads();

    for (int c = 0; c < KCHUNKS; c++) {
        const uint32_t base = bufs + (c & 1) * 65536;
        if (c + 1 < KCHUNKS) {
            const int k64 = (c + 1) << 6;
            load_tiles(Ahp + k64, Alp + k64, Bhp + k64, Blp + k64, K,
                       bufs + ((c + 1) & 1) * 65536);
        }
        const uint32_t bAh = base, bAl = base + 16384, bBh = base + 32768, bBl = base + 49152;

        #pragma unroll
        for (int ks = 0; ks < 4; ks++) {
            const uint32_t kb  = (uint32_t)ks * 32;
            const uint32_t kcA = (kb + adk) ^ sw;
            const uint32_t kcB = (kb + bdk) ^ sw;

            uint32_t ah[4][4], al[4][4], bhx[2][4], blx[2][4];
            #pragma unroll
            for (int mt = 0; mt < 4; mt++) {
                ldsm4(bAh + aro[mt] + kcA, ah[mt]);
                ldsm4(bAl + aro[mt] + kcA, al[mt]);
            }
            #pragma unroll
            for (int np = 0; np < 2; np++) {
                ldsm4(bBh + bro[np] + kcB, bhx[np]);
                ldsm4(bBl + bro[np] + kcB, blx[np]);
            }
            #pragma unroll
            for (int mt = 0; mt < 4; mt++)
                #pragma unroll
                for (int nt = 0; nt < 4; nt++) {
                    const uint32_t* bh2 = &bhx[nt >> 1][(nt & 1) * 2];
                    const uint32_t* bl2 = &blx[nt >> 1][(nt & 1) * 2];
                    mma16816(acc[mt][nt], ah[mt], bh2);
                    mma16816(acc[mt][nt], ah[mt], bl2);
                    mma16816(acc[mt][nt], al[mt], bh2);
                }
        }
        __syncthreads();
    }

    // epilogue
    const int which = n0 >> 11;
    const int h     = (n0 >> 7) & 15;

    #pragma unroll
    for (int mt = 0; mt < 4; mt++) {
        const int mrow = m0 + wr*64 + mt*16 + (lane >> 2);
        #pragma unroll
        for (int nt = 0; nt < 4; nt++) {
            const int cl = wc*32 + nt*8 + (lane & 3)*2;
            const int cg = n0 + cl;
            const float bx = bias[cg], by = bias[cg + 1];
            float2 v0 = make_float2(acc[mt][nt][0] + bx, acc[mt][nt][1] + by);
            float2 v1 = make_float2(acc[mt][nt][2] + bx, acc[mt][nt][3] + by);
            if (MODE == 1) {
                const int b0r = mrow >> 11, l0r = mrow & (SEQ - 1);
                const int m1  = mrow + 8;
                const int b1r = m1 >> 11,   l1r = m1 & (SEQ - 1);
                const size_t i0 = (((size_t)(b0r*NHEAD + h))*SEQ + l0r)*HDIM + cl;
                const size_t i1 = (((size_t)(b1r*NHEAD + h))*SEQ + l1r)*HDIM + cl;
                if (which == 2) {
                    uint32_t hi, lo;
                    split2(v0.x, v0.y, hi, lo);
                    *(uint32_t*)&g_vbh[i0] = hi; *(uint32_t*)&g_vbl[i0] = lo;
                    split2(v1.x, v1.y, hi, lo);
                    *(uint32_t*)&g_vbh[i1] = hi; *(uint32_t*)&g_vbl[i1] = lo;
                } else {
                    float* qk = (which == 0) ? g_q : g_k;
                    *(float2*)&qk[i0] = v0;
                    *(float2*)&qk[i1] = v1;
                }
            } else {
                *(float2*)&C[(size_t)mrow * N + cg]       = v0;
                *(float2*)&C[(size_t)(mrow + 8) * N + cg] = v1;
            }
        }
    }
}

// ---------------------------------------------------------------------------
// RoPE: reads fp32 g_q/g_k, writes bf16 hi/lo (Q scaled by 1/sqrt(128)).
// ---------------------------------------------------------------------------
__global__ void rope_kernel()
{
    const int total = BATCH*NHEAD*SEQ*64;
    int idx = blockIdx.x * blockDim.x + threadIdx.x;
    if (idx >= total) return;
    const int d    = idx & 63;
    const int rowi = idx >> 6;
    const int l    = rowi & (SEQ - 1);

    double invf = exp2(-(double)d * (13.287712379549449 / 64.0)); // 10000^(-d/64)
    double t    = fmod((double)l * invf, 6.283185307179586476925286766559);
    float c = cosf((float)t);
    float s = sinf((float)t);

    const size_t base = (size_t)rowi * HDIM;
    const float qs = 0.08838834764831845f;

    float q1 = g_q[base + d], q2 = g_q[base + d + 64];
    float k1 = g_k[base + d], k2 = g_k[base + d + 64];
    float qo1 = (q1*c - q2*s) * qs, qo2 = (q2*c + q1*s) * qs;
    float ko1 = k1*c - k2*s,       ko2 = k2*c + k1*s;

    __nv_bfloat16 h;
    h = __float2bfloat16(qo1); g_qbh[base+d]    = h; g_qbl[base+d]    = __float2bfloat16(qo1 - __bfloat162float(h));
    h = __float2bfloat16(qo2); g_qbh[base+d+64] = h; g_qbl[base+d+64] = __float2bfloat16(qo2 - __bfloat162float(h));
    h = __float2bfloat16(ko1); g_kbh[base+d]    = h; g_kbl[base+d]    = __float2bfloat16(ko1 - __bfloat162float(h));
    h = __float2bfloat16(ko2); g_kbh[base+d+64] = h; g_kbl[base+d+64] = __float2bfloat16(ko2 - __bfloat162float(h));
}

// ---------------------------------------------------------------------------
// HMMA causal flash attention. BQ=128, BK=64, 8 warps (16 q-rows each).
// S = Qh Kh^T + Qh Kl^T + Ql Kh^T ; P split hi/lo ; O += Ph Vh + Ph Vl + Pl Vh
// smem: Q panels 64KB + double-buffered KV 2x64KB. cp.async pipeline.
// Output written as bf16 hi/lo to g_ah/g_al in [B, L, H*128].
// ---------------------------------------------------------------------------
__global__ __launch_bounds__(256, 1)
void attn_kernel()
{
    extern __shared__ char sm[];
    const uint32_t base = (smem_u32(sm) + 1023) & ~1023u;
    const uint32_t QH = base;                 // 2 panels x 16KB (dims 0-63, 64-127)
    const uint32_t QL = base + 32768;
    const uint32_t KV = base + 65536;         // buf b: +b*65536: Kh,Kl,Vh,Vl (16KB each)

    const int tid  = threadIdx.x;
    const int lane = tid & 31;
    const int wid  = tid >> 5;
    const int qt   = (int)gridDim.x - 1 - (int)blockIdx.x;  // heavy tiles first
    const int h    = blockIdx.y;
    const int b    = blockIdx.z;
    const int bh   = b*NHEAD + h;
    const int q0   = qt << 7;
    const int nkv  = 2*qt + 2;

    const size_t hoff = (size_t)bh * SEQ * HDIM;
    const __nv_bfloat16* qbh = g_qbh + hoff + (size_t)q0 * HDIM;
    const __nv_bfloat16* qbl = g_qbl + hoff + (size_t)q0 * HDIM;
    const __nv_bfloat16* kbh = g_kbh + hoff;
    const __nv_bfloat16* kbl = g_kbl + hoff;
    const __nv_bfloat16* vbh = g_vbh + hoff;
    const __nv_bfloat16* vbl = g_vbl + hoff;

    // ---- Q load (once): 2 arrays x (128 rows x 16 16B-units) ----
    #pragma unroll
    for (int it = 0; it < 8; it++) {
        int i = tid + it * 256;           // 0..2047
        int row = i >> 4, u = i & 15;
        uint32_t off = (u >> 3) * 16384 + SWZ(row * 128 + (u & 7) * 16);
        const __nv_bfloat16* s0 = qbh + (size_t)row * HDIM + u * 8;
        const __nv_bfloat16* s1 = qbl + (size_t)row * HDIM + u * 8;
        CP16(QH + off, s0);
        CP16(QL + off, s1);
    }
    // ---- KV prefetch block 0 ----
    {
        const __nv_bfloat16* arr[4] = {kbh, kbl, vbh, vbl};
        #pragma unroll
        for (int t = 0; t < 4; t++)
            #pragma unroll
            for (int it = 0; it < 4; it++) {
                int i = tid + it * 256;   // 0..1023
                int row = i >> 4, u = i & 15;
                uint32_t d = KV + t*16384 + (u>>3)*8192 + SWZ(row*128 + (u&7)*16);
                CP16(d, arr[t] + (size_t)row * HDIM + u * 8);
            }
    }
    CP_COMMIT();

    // per-thread softmax state (2 rows, replicated in quad)
    float mr0 = -1e30f, mr1 = -1e30f, lr0 = 0.f, lr1 = 0.f;
    float o[16][4];
    #pragma unroll
    for (int t = 0; t < 16; t++)
        #pragma unroll
        for (int j = 0; j < 4; j++) o[t][j] = 0.f;

    const int rloc0 = wid*16 + (lane >> 2);        // local q row (first)
    const int rg0   = q0 + rloc0;                  // global q row

    for (int kt = 0; kt < nkv; kt++) {
        CP_WAIT0();
        __syncthreads();

        const uint32_t KB = KV + (kt & 1) * 65536;        // Kh
        const uint32_t VB = KB + 32768;                   // Vh

        if (kt + 1 < nkv) {
            const __nv_bfloat16* arr[4] = {kbh, kbl, vbh, vbl};
            const size_t s0 = (size_t)(kt + 1) * 64 * HDIM;
            const uint32_t nb = KV + ((kt + 1) & 1) * 65536;
            #pragma unroll
            for (int t = 0; t < 4; t++)
                #pragma unroll
                for (int it = 0; it < 4; it++) {
                    int i = tid + it * 256;
                    int row = i >> 4, u = i & 15;
                    uint32_t d = nb + t*16384 + (u>>3)*8192 + SWZ(row*128 + (u&7)*16);
                    CP16(d, arr[t] + s0 + (size_t)row * HDIM + u * 8);
                }
            CP_COMMIT();
        }

        // ---- S = Q K^T (per warp: 16 x 64) ----
        float s[8][4];
        #pragma unroll
        for (int t = 0; t < 8; t++)
            #pragma unroll
            for (int j = 0; j < 4; j++) s[t][j] = 0.f;

        #pragma unroll
        for (int ks = 0; ks < 8; ks++) {
            const int arow = wid*16 + (lane & 15);
            const uint32_t aoff = (ks>>2)*16384
                + SWZ(arow*128 + (ks&3)*32 + ((lane>>4)<<4));
            uint32_t qa[4], qla[4];
            ldsm4(QH + aoff, qa);
            ldsm4(QL + aoff, qla);

            const int krow0 = (lane & 7) + ((lane >> 4) << 3);
            const uint32_t kcol = (uint32_t)((ks&3)*32 + (((lane>>3)&1)<<4));
            #pragma unroll
            for (int ntp = 0; ntp < 4; ntp++) {
                const uint32_t koff = (ks>>2)*8192 + SWZ((ntp*16 + krow0)*128 + kcol);
                uint32_t kb4[4], klb4[4];
                ldsm4(KB + koff, kb4);
                ldsm4(KB + 16384 + koff, klb4);
                mma16816(s[2*ntp],   qa,  &kb4[0]);
                mma16816(s[2*ntp],   qa,  &klb4[0]);
                mma16816(s[2*ntp],   qla, &kb4[0]);
                mma16816(s[2*ntp+1], qa,  &kb4[2]);
                mma16816(s[2*ntp+1], qa,  &klb4[2]);
                mma16816(s[2*ntp+1], qla, &kb4[2]);
            }
        }

        // ---- causal mask (only near the diagonal) ----
        if (kt >= 2*qt) {
            #pragma unroll
            for (int t = 0; t < 8; t++) {
                #pragma unroll
                for (int j = 0; j < 2; j++) {
                    const int n = kt*64 + t*8 + 2*(lane & 3) + j;
                    if (n > rg0)     s[t][j]   = -1e30f;
                    if (n > rg0 + 8) s[t][2+j] = -1e30f;
                }
            }
        }

        // ---- online softmax ----
        float rm0 = -1e30f, rm1 = -1e30f;
        #pragma unroll
        for (int t = 0; t < 8; t++) {
            rm0 = fmaxf(rm0, fmaxf(s[t][0], s[t][1]));
            rm1 = fmaxf(rm1, fmaxf(s[t][2], s[t][3]));
        }
        rm0 = fmaxf(rm0, __shfl_xor_sync(0xffffffffu, rm0, 1));
        rm0 = fmaxf(rm0, __shfl_xor_sync(0xffffffffu, rm0, 2));
        rm1 = fmaxf(rm1, __shfl_xor_sync(0xffffffffu, rm1, 1));
        rm1 = fmaxf(rm1, __shfl_xor_sync(0xffffffffu, rm1, 2));

        const float mn0 = fmaxf(mr0, rm0), mn1 = fmaxf(mr1, rm1);
        const float sf0 = __expf(mr0 - mn0), sf1 = __expf(mr1 - mn1);
        mr0 = mn0; mr1 = mn1;

        float rs0 = 0.f, rs1 = 0.f;
        #pragma unroll
        for (int t = 0; t < 8; t++) {
            s[t][0] = __expf(s[t][0] - mn0);
            s[t][1] = __expf(s[t][1] - mn0);
            s[t][2] = __expf(s[t][2] - mn1);
            s[t][3] = __expf(s[t][3] - mn1);
            rs0 += s[t][0] + s[t][1];
            rs1 += s[t][2] + s[t][3];
        }
        rs0 += __shfl_xor_sync(0xffffffffu, rs0, 1);
        rs0 += __shfl_xor_sync(0xffffffffu, rs0, 2);
        rs1 += __shfl_xor_sync(0xffffffffu, rs1, 1);
        rs1 += __shfl_xor_sync(0xffffffffu, rs1, 2);
        lr0 = lr0 * sf0 + rs0;
        lr1 = lr1 * sf1 + rs1;

        // rescale O
        #pragma unroll
        for (int t = 0; t < 16; t++) {
            o[t][0] *= sf0; o[t][1] *= sf0;
            o[t][2] *= sf1; o[t][3] *= sf1;
        }

        // ---- pack P into hi/lo A-fragments ----
        uint32_t aph[4][4], apl[4][4];
        #pragma unroll
        for (int g = 0; g < 4; g++) {
            split2(s[2*g][0],   s[2*g][1],   aph[g][0], apl[g][0]);
            split2(s[2*g][2],   s[2*g][3],   aph[g][1], apl[g][1]);
            split2(s[2*g+1][0], s[2*g+1][1], aph[g][2], apl[g][2]);
            split2(s[2*g+1][2], s[2*g+1][3], aph[g][3], apl[g][3]);
        }

        // ---- O += P V ----
        const int vrow0 = (lane & 15);
        const uint32_t vcadd = (uint32_t)((lane >> 4) << 4);
        #pragma unroll
        for (int dtp = 0; dtp < 8; dtp++) {
            const uint32_t vcol = (uint32_t)((dtp&3)*32) + vcadd;
            #pragma unroll
            for (int g = 0; g < 4; g++) {
                const uint32_t voff = (dtp>>2)*8192 + SWZ((g*16 + vrow0)*128 + vcol);
                uint32_t vb4[4], vlb4[4];
                ldsm4t(VB + voff, vb4);
                ldsm4t(VB + 16384 + voff, vlb4);
                mma16816(o[2*dtp],   aph[g], &vb4[0]);
                mma16816(o[2*dtp],   aph[g], &vlb4[0]);
                mma16816(o[2*dtp],   apl[g], &vb4[0]);
                mma16816(o[2*dtp+1], aph[g], &vb4[2]);
                mma16816(o[2*dtp+1], aph[g], &vlb4[2]);
                mma16816(o[2*dtp+1], apl[g], &vb4[2]);
            }
        }
        __syncthreads();
    }

    // ---- epilogue: normalize, split hi/lo, write [B, L, H*128] ----
    const float inv0 = 1.f / lr0, inv1 = 1.f / lr1;
    const size_t row0 = ((size_t)(b*SEQ + rg0)) * D_MODEL + h*HDIM;
    const size_t row1 = row0 + 8 * D_MODEL;
    #pragma unroll
    for (int t = 0; t < 16; t++) {
        const int d = t*8 + 2*(lane & 3);
        uint32_t hi, lo;
        split2(o[t][0]*inv0, o[t][1]*inv0, hi, lo);
        *(uint32_t*)&g_ah[row0 + d] = hi;
        *(uint32_t*)&g_al[row0 + d] = lo;
        split2(o[t][2]*inv1, o[t][3]*inv1, hi, lo);
        *(uint32_t*)&g_ah[row1 + d] = hi;
        *(uint32_t*)&g_al[row1 + d] = lo;
    }
}

// ---------------------------------------------------------------------------
extern "C" void kernel_launch(void* const* d_in, const int* in_sizes, int n_in,
                              void* d_out, int out_size)
{
    const float* query = (const float*)d_in[0];
    const float* W_qkv = (const float*)d_in[1];
    const float* b_qkv = (const float*)d_in[2];
    const float* W_out = (const float*)d_in[3];
    const float* b_out = (const float*)d_in[4];
    float* out = (float*)d_out;

    void *p_qh, *p_ql, *p_wh, *p_wl, *p_oh, *p_ol, *p_ah, *p_al;
    cudaGetSymbolAddress(&p_qh, g_qh);  cudaGetSymbolAddress(&p_ql, g_ql);
    cudaGetSymbolAddress(&p_wh, g_wh);  cudaGetSymbolAddress(&p_wl, g_wl);
    cudaGetSymbolAddress(&p_oh, g_oh);  cudaGetSymbolAddress(&p_ol, g_ol);
    cudaGetSymbolAddress(&p_ah, g_ah);  cudaGetSymbolAddress(&p_al, g_al);

    const int GEMM_SMEM = 1024 + 2*65536;
    cudaFuncSetAttribute(tc_gemm<0>, cudaFuncAttributeMaxDynamicSharedMemorySize, GEMM_SMEM);
    cudaFuncSetAttribute(tc_gemm<1>, cudaFuncAttributeMaxDynamicSharedMemorySize, GEMM_SMEM);
    const int ATTN_SMEM = 1024 + 65536 + 2*65536;   // Q + double KV
    cudaFuncSetAttribute(attn_kernel, cudaFuncAttributeMaxDynamicSharedMemorySize, ATTN_SMEM);

    // 1) split inputs into bf16 hi/lo
    {
        int n;
        n = MROWS*D_MODEL;
        split_kernel<<<n/1024, 256>>>(query, (__nv_bfloat16*)p_qh, (__nv_bfloat16*)p_ql, n);
        n = 3*D_MODEL*D_MODEL;
        split_kernel<<<n/1024, 256>>>(W_qkv, (__nv_bfloat16*)p_wh, (__nv_bfloat16*)p_wl, n);
        n = D_MODEL*D_MODEL;
        split_kernel<<<n/1024, 256>>>(W_out, (__nv_bfloat16*)p_oh, (__nv_bfloat16*)p_ol, n);
    }

    // 2) QKV projection (HMMA): q,k fp32; v bf16 hi/lo
    tc_gemm<1><<<dim3(3*D_MODEL/128, MROWS/128), 256, GEMM_SMEM>>>(
        (const __nv_bfloat16*)p_qh, (const __nv_bfloat16*)p_ql,
        (const __nv_bfloat16*)p_wh, (const __nv_bfloat16*)p_wl,
        b_qkv, nullptr, 3*D_MODEL, D_MODEL);

    // 3) RoPE -> bf16 hi/lo Q,K
    rope_kernel<<<(BATCH*NHEAD*SEQ*64)/256, 256>>>();

    // 4) HMMA causal flash attention -> g_ah/g_al
    attn_kernel<<<dim3(SEQ/128, NHEAD, BATCH), 256, ATTN_SMEM>>>();

    // 5) Output projection (HMMA) -> d_out
    tc_gemm<0><<<dim3(D_MODEL/128, MROWS/128), 256, GEMM_SMEM>>>(
        (const __nv_bfloat16*)p_ah, (const __nv_bfloat16*)p_al,
        (const __nv_bfloat16*)p_oh, (const __nv_bfloat16*)p_ol,
        b_out, out, D_MODEL, D_MODEL);
}

// round 5
// speedup vs baseline: 4.0961x; 1.2243x over previous
#include <cuda_runtime.h>
#include <cuda_bf16.h>
#include <math.h>
#include <stdint.h>

#define D_MODEL 2048
#define NHEAD   16
#define HDIM    128
#define BATCH   2
#define SEQ     2048
#define MROWS   (BATCH*SEQ)   // 4096

// ---------------- device scratch (no runtime allocation) ----------------
__device__ float g_q[(size_t)BATCH*NHEAD*SEQ*HDIM];     // fp32 pre-rope Q
__device__ float g_k[(size_t)BATCH*NHEAD*SEQ*HDIM];     // fp32 pre-rope K

__device__ __nv_bfloat16 g_qbh[(size_t)BATCH*NHEAD*SEQ*HDIM];  // roped+scaled Q hi/lo
__device__ __nv_bfloat16 g_qbl[(size_t)BATCH*NHEAD*SEQ*HDIM];
__device__ __nv_bfloat16 g_kbh[(size_t)BATCH*NHEAD*SEQ*HDIM];  // roped K hi/lo
__device__ __nv_bfloat16 g_kbl[(size_t)BATCH*NHEAD*SEQ*HDIM];
__device__ __nv_bfloat16 g_vbh[(size_t)BATCH*NHEAD*SEQ*HDIM];  // V hi/lo
__device__ __nv_bfloat16 g_vbl[(size_t)BATCH*NHEAD*SEQ*HDIM];

__device__ __nv_bfloat16 g_qh[(size_t)MROWS*D_MODEL];       // query hi/lo (GEMM A)
__device__ __nv_bfloat16 g_ql[(size_t)MROWS*D_MODEL];
__device__ __nv_bfloat16 g_wh[(size_t)3*D_MODEL*D_MODEL];   // W_qkv hi/lo
__device__ __nv_bfloat16 g_wl[(size_t)3*D_MODEL*D_MODEL];
__device__ __nv_bfloat16 g_oh[(size_t)D_MODEL*D_MODEL];     // W_out hi/lo
__device__ __nv_bfloat16 g_ol[(size_t)D_MODEL*D_MODEL];
__device__ __nv_bfloat16 g_ah[(size_t)MROWS*D_MODEL];       // attn-out hi/lo
__device__ __nv_bfloat16 g_al[(size_t)MROWS*D_MODEL];

// ---------------- helpers ----------------
__device__ __forceinline__ uint32_t smem_u32(const void* p) {
    uint32_t a;
    asm("{ .reg .u64 t; cvta.to.shared.u64 t, %1; cvt.u32.u64 %0, t; }" : "=r"(a) : "l"(p));
    return a;
}
#define SWZ(o) ((o) ^ (((o) >> 3) & 0x70))

__device__ __forceinline__ void ldsm4(uint32_t addr, uint32_t* r) {
    asm volatile("ldmatrix.sync.aligned.m8n8.x4.shared.b16 {%0,%1,%2,%3}, [%4];"
                 : "=r"(r[0]), "=r"(r[1]), "=r"(r[2]), "=r"(r[3]) : "r"(addr));
}
__device__ __forceinline__ void ldsm4t(uint32_t addr, uint32_t* r) {
    asm volatile("ldmatrix.sync.aligned.m8n8.x4.trans.shared.b16 {%0,%1,%2,%3}, [%4];"
                 : "=r"(r[0]), "=r"(r[1]), "=r"(r[2]), "=r"(r[3]) : "r"(addr));
}
__device__ __forceinline__ void mma16816(float* c, const uint32_t* a, const uint32_t* b) {
    asm volatile(
        "mma.sync.aligned.m16n8k16.row.col.f32.bf16.bf16.f32 "
        "{%0,%1,%2,%3}, {%4,%5,%6,%7}, {%8,%9}, {%0,%1,%2,%3};"
        : "+f"(c[0]), "+f"(c[1]), "+f"(c[2]), "+f"(c[3])
        : "r"(a[0]), "r"(a[1]), "r"(a[2]), "r"(a[3]), "r"(b[0]), "r"(b[1]));
}
#define CP16(dst, src) \
    asm volatile("cp.async.cg.shared.global [%0], [%1], 16;" :: "r"(dst), "l"(src))
#define CP_COMMIT() asm volatile("cp.async.commit_group;" ::: "memory")
#define CP_WAIT0()  asm volatile("cp.async.wait_group 0;" ::: "memory")
#define CP_WAIT1()  asm volatile("cp.async.wait_group 1;" ::: "memory")

// split pair of fp32 into packed bf16x2 hi and lo (residual)
__device__ __forceinline__ void split2(float x, float y, uint32_t& hi, uint32_t& lo) {
    __nv_bfloat16 hx = __float2bfloat16(x), hy = __float2bfloat16(y);
    float rx = x - __bfloat162float(hx), ry = y - __bfloat162float(hy);
    __nv_bfloat16 lx = __float2bfloat16(rx), ly = __float2bfloat16(ry);
    hi = ((uint32_t)__bfloat16_as_ushort(hy) << 16) | __bfloat16_as_ushort(hx);
    lo = ((uint32_t)__bfloat16_as_ushort(ly) << 16) | __bfloat16_as_ushort(lx);
}

// ---------------------------------------------------------------------------
// fp32 -> bf16 hi/lo split
// ---------------------------------------------------------------------------
__global__ void split_kernel(const float* __restrict__ x,
                             __nv_bfloat16* __restrict__ hi,
                             __nv_bfloat16* __restrict__ lo, int n)
{
    int i = (blockIdx.x * 256 + threadIdx.x) * 4;
    if (i >= n) return;
    float4 v = *(const float4*)(x + i);
    uint32_t h0, l0, h1, l1;
    split2(v.x, v.y, h0, l0);
    split2(v.z, v.w, h1, l1);
    *(uint2*)(hi + i) = make_uint2(h0, h1);
    *(uint2*)(lo + i) = make_uint2(l0, l1);
}

// ---------------------------------------------------------------------------
// HMMA GEMM with cp.async double-buffered pipeline.
// C = Ah*Bh^T + Ah*Bl^T + Al*Bh^T + bias   (fp32 accum)
// CTA 128x128, 8 warps, K-chunks of 64 bf16, SW128 smem.
// MODE 0: write C fp32 row-major.
// MODE 1: QKV: q,k -> fp32 [B,H,L,128]; v -> bf16 hi/lo [B,H,L,128].
// ---------------------------------------------------------------------------
__device__ __forceinline__ void load_tiles_async(
    const __nv_bfloat16* __restrict__ a0, const __nv_bfloat16* __restrict__ a1,
    const __nv_bfloat16* __restrict__ b0, const __nv_bfloat16* __restrict__ b1,
    int K, uint32_t dst)
{
    const __nv_bfloat16* s[4] = {a0, a1, b0, b1};
    #pragma unroll
    for (int t = 0; t < 4; t++) {
        uint32_t d = dst + t * 16384;
        const __nv_bfloat16* p = s[t];
        #pragma unroll
        for (int it = 0; it < 4; it++) {
            int i = threadIdx.x + it * 256;        // 0..1023 (16B units)
            int r = i >> 3, c = i & 7;
            CP16(d + SWZ(r * 128 + c * 16), p + (size_t)r * K + c * 8);
        }
    }
}

template<int MODE>
__global__ __launch_bounds__(256, 1)
void tc_gemm(const __nv_bfloat16* __restrict__ Ah, const __nv_bfloat16* __restrict__ Al,
             const __nv_bfloat16* __restrict__ Bh, const __nv_bfloat16* __restrict__ Bl,
             const float* __restrict__ bias, float* __restrict__ C, int N, int K)
{
    extern __shared__ char smem[];
    const uint32_t bufs = (smem_u32(smem) + 1023) & ~1023u;

    const int tid  = threadIdx.x;
    const int lane = tid & 31;
    const int wid  = tid >> 5;
    const int wr   = wid >> 2;
    const int wc   = wid & 3;
    const int m0   = blockIdx.y << 7;
    const int n0   = blockIdx.x << 7;
    const int KCHUNKS = K >> 6;

    const __nv_bfloat16* Ahp = Ah + (size_t)m0 * K;
    const __nv_bfloat16* Alp = Al + (size_t)m0 * K;
    const __nv_bfloat16* Bhp = Bh + (size_t)n0 * K;
    const __nv_bfloat16* Blp = Bl + (size_t)n0 * K;

    float acc[4][4][4];
    #pragma unroll
    for (int i = 0; i < 4; i++)
        #pragma unroll
        for (int j = 0; j < 4; j++)
            #pragma unroll
            for (int r = 0; r < 4; r++) acc[i][j][r] = 0.f;

    const uint32_t sw   = (lane & 7) << 4;
    const int      arow = lane & 15;
    const uint32_t adk  = (lane >> 4) << 4;
    const int      brow = (lane & 7) + ((lane >> 4) << 3);
    const uint32_t bdk  = ((lane >> 3) & 1) << 4;

    uint32_t aro[4], bro[2];
    #pragma unroll
    for (int mt = 0; mt < 4; mt++) aro[mt] = (uint32_t)(wr*64 + mt*16 + arow) * 128;
    #pragma unroll
    for (int np = 0; np < 2; np++) bro[np] = (uint32_t)(wc*32 + np*16 + brow) * 128;

    // prologue: async load chunk 0 -> buffer 0
    load_tiles_async(Ahp, Alp, Bhp, Blp, K, bufs);
    CP_COMMIT();

    for (int c = 0; c < KCHUNKS; c++) {
        const uint32_t base = bufs + (c & 1) * 65536;
        if (c + 1 < KCHUNKS) {
            const int k64 = (c + 1) << 6;
            load_tiles_async(Ahp + k64, Alp + k64, Bhp + k64, Blp + k64, K,
                             bufs + ((c + 1) & 1) * 65536);
            CP_COMMIT();
            CP_WAIT1();     // chunk c resident; chunk c+1 in flight
        } else {
            CP_WAIT0();
        }
        __syncthreads();

        const uint32_t bAh = base, bAl = base + 16384, bBh = base + 32768, bBl = base + 49152;

        #pragma unroll
        for (int ks = 0; ks < 4; ks++) {
            const uint32_t kb  = (uint32_t)ks * 32;
            const uint32_t kcA = (kb + adk) ^ sw;
            const uint32_t kcB = (kb + bdk) ^ sw;

            uint32_t ah[4][4], al[4][4], bhx[2][4], blx[2][4];
            #pragma unroll
            for (int mt = 0; mt < 4; mt++) {
                ldsm4(bAh + aro[mt] + kcA, ah[mt]);
                ldsm4(bAl + aro[mt] + kcA, al[mt]);
            }
            #pragma unroll
            for (int np = 0; np < 2; np++) {
                ldsm4(bBh + bro[np] + kcB, bhx[np]);
                ldsm4(bBl + bro[np] + kcB, blx[np]);
            }
            #pragma unroll
            for (int mt = 0; mt < 4; mt++)
                #pragma unroll
                for (int nt = 0; nt < 4; nt++) {
                    const uint32_t* bh2 = &bhx[nt >> 1][(nt & 1) * 2];
                    const uint32_t* bl2 = &blx[nt >> 1][(nt & 1) * 2];
                    mma16816(acc[mt][nt], ah[mt], bh2);
                    mma16816(acc[mt][nt], ah[mt], bl2);
                    mma16816(acc[mt][nt], al[mt], bh2);
                }
        }
        __syncthreads();   // protect buffer c (reloaded at c+2) from early overwrite
    }

    // epilogue
    const int which = n0 >> 11;
    const int h     = (n0 >> 7) & 15;

    #pragma unroll
    for (int mt = 0; mt < 4; mt++) {
        const int mrow = m0 + wr*64 + mt*16 + (lane >> 2);
        #pragma unroll
        for (int nt = 0; nt < 4; nt++) {
            const int cl = wc*32 + nt*8 + (lane & 3)*2;
            const int cg = n0 + cl;
            const float bx = bias[cg], by = bias[cg + 1];
            float2 v0 = make_float2(acc[mt][nt][0] + bx, acc[mt][nt][1] + by);
            float2 v1 = make_float2(acc[mt][nt][2] + bx, acc[mt][nt][3] + by);
            if (MODE == 1) {
                const int b0r = mrow >> 11, l0r = mrow & (SEQ - 1);
                const int m1  = mrow + 8;
                const int b1r = m1 >> 11,   l1r = m1 & (SEQ - 1);
                const size_t i0 = (((size_t)(b0r*NHEAD + h))*SEQ + l0r)*HDIM + cl;
                const size_t i1 = (((size_t)(b1r*NHEAD + h))*SEQ + l1r)*HDIM + cl;
                if (which == 2) {
                    uint32_t hi, lo;
                    split2(v0.x, v0.y, hi, lo);
                    *(uint32_t*)&g_vbh[i0] = hi; *(uint32_t*)&g_vbl[i0] = lo;
                    split2(v1.x, v1.y, hi, lo);
                    *(uint32_t*)&g_vbh[i1] = hi; *(uint32_t*)&g_vbl[i1] = lo;
                } else {
                    float* qk = (which == 0) ? g_q : g_k;
                    *(float2*)&qk[i0] = v0;
                    *(float2*)&qk[i1] = v1;
                }
            } else {
                *(float2*)&C[(size_t)mrow * N + cg]       = v0;
                *(float2*)&C[(size_t)(mrow + 8) * N + cg] = v1;
            }
        }
    }
}

// ---------------------------------------------------------------------------
// RoPE: reads fp32 g_q/g_k, writes bf16 hi/lo (Q scaled by 1/sqrt(128)).
// ---------------------------------------------------------------------------
__global__ void rope_kernel()
{
    const int total = BATCH*NHEAD*SEQ*64;
    int idx = blockIdx.x * blockDim.x + threadIdx.x;
    if (idx >= total) return;
    const int d    = idx & 63;
    const int rowi = idx >> 6;
    const int l    = rowi & (SEQ - 1);

    double invf = exp2(-(double)d * (13.287712379549449 / 64.0)); // 10000^(-d/64)
    double t    = fmod((double)l * invf, 6.283185307179586476925286766559);
    float c = cosf((float)t);
    float s = sinf((float)t);

    const size_t base = (size_t)rowi * HDIM;
    const float qs = 0.08838834764831845f;

    float q1 = g_q[base + d], q2 = g_q[base + d + 64];
    float k1 = g_k[base + d], k2 = g_k[base + d + 64];
    float qo1 = (q1*c - q2*s) * qs, qo2 = (q2*c + q1*s) * qs;
    float ko1 = k1*c - k2*s,       ko2 = k2*c + k1*s;

    __nv_bfloat16 h;
    h = __float2bfloat16(qo1); g_qbh[base+d]    = h; g_qbl[base+d]    = __float2bfloat16(qo1 - __bfloat162float(h));
    h = __float2bfloat16(qo2); g_qbh[base+d+64] = h; g_qbl[base+d+64] = __float2bfloat16(qo2 - __bfloat162float(h));
    h = __float2bfloat16(ko1); g_kbh[base+d]    = h; g_kbl[base+d]    = __float2bfloat16(ko1 - __bfloat162float(h));
    h = __float2bfloat16(ko2); g_kbh[base+d+64] = h; g_kbl[base+d+64] = __float2bfloat16(ko2 - __bfloat162float(h));
}

// ---------------------------------------------------------------------------
// HMMA causal flash attention. BQ=128, BK=64, 8 warps (16 q-rows each).
// ---------------------------------------------------------------------------
__global__ __launch_bounds__(256, 1)
void attn_kernel()
{
    extern __shared__ char sm[];
    const uint32_t base = (smem_u32(sm) + 1023) & ~1023u;
    const uint32_t QH = base;                 // 2 panels x 16KB (dims 0-63, 64-127)
    const uint32_t QL = base + 32768;
    const uint32_t KV = base + 65536;         // buf b: +b*65536: Kh,Kl,Vh,Vl (16KB each)

    const int tid  = threadIdx.x;
    const int lane = tid & 31;
    const int wid  = tid >> 5;
    const int qt   = (int)gridDim.x - 1 - (int)blockIdx.x;  // heavy tiles first
    const int h    = blockIdx.y;
    const int b    = blockIdx.z;
    const int bh   = b*NHEAD + h;
    const int q0   = qt << 7;
    const int nkv  = 2*qt + 2;

    const size_t hoff = (size_t)bh * SEQ * HDIM;
    const __nv_bfloat16* qbh = g_qbh + hoff + (size_t)q0 * HDIM;
    const __nv_bfloat16* qbl = g_qbl + hoff + (size_t)q0 * HDIM;
    const __nv_bfloat16* kbh = g_kbh + hoff;
    const __nv_bfloat16* kbl = g_kbl + hoff;
    const __nv_bfloat16* vbh = g_vbh + hoff;
    const __nv_bfloat16* vbl = g_vbl + hoff;

    #pragma unroll
    for (int it = 0; it < 8; it++) {
        int i = tid + it * 256;
        int row = i >> 4, u = i & 15;
        uint32_t off = (u >> 3) * 16384 + SWZ(row * 128 + (u & 7) * 16);
        CP16(QH + off, qbh + (size_t)row * HDIM + u * 8);
        CP16(QL + off, qbl + (size_t)row * HDIM + u * 8);
    }
    {
        const __nv_bfloat16* arr[4] = {kbh, kbl, vbh, vbl};
        #pragma unroll
        for (int t = 0; t < 4; t++)
            #pragma unroll
            for (int it = 0; it < 4; it++) {
                int i = tid + it * 256;
                int row = i >> 4, u = i & 15;
                uint32_t d = KV + t*16384 + (u>>3)*8192 + SWZ(row*128 + (u&7)*16);
                CP16(d, arr[t] + (size_t)row * HDIM + u * 8);
            }
    }
    CP_COMMIT();

    float mr0 = -1e30f, mr1 = -1e30f, lr0 = 0.f, lr1 = 0.f;
    float o[16][4];
    #pragma unroll
    for (int t = 0; t < 16; t++)
        #pragma unroll
        for (int j = 0; j < 4; j++) o[t][j] = 0.f;

    const int rloc0 = wid*16 + (lane >> 2);
    const int rg0   = q0 + rloc0;

    for (int kt = 0; kt < nkv; kt++) {
        CP_WAIT0();
        __syncthreads();

        const uint32_t KB = KV + (kt & 1) * 65536;
        const uint32_t VB = KB + 32768;

        if (kt + 1 < nkv) {
            const __nv_bfloat16* arr[4] = {kbh, kbl, vbh, vbl};
            const size_t s0 = (size_t)(kt + 1) * 64 * HDIM;
            const uint32_t nb = KV + ((kt + 1) & 1) * 65536;
            #pragma unroll
            for (int t = 0; t < 4; t++)
                #pragma unroll
                for (int it = 0; it < 4; it++) {
                    int i = tid + it * 256;
                    int row = i >> 4, u = i & 15;
                    uint32_t d = nb + t*16384 + (u>>3)*8192 + SWZ(row*128 + (u&7)*16);
                    CP16(d, arr[t] + s0 + (size_t)row * HDIM + u * 8);
                }
            CP_COMMIT();
        }

        float s[8][4];
        #pragma unroll
        for (int t = 0; t < 8; t++)
            #pragma unroll
            for (int j = 0; j < 4; j++) s[t][j] = 0.f;

        #pragma unroll
        for (int ks = 0; ks < 8; ks++) {
            const int arow = wid*16 + (lane & 15);
            const uint32_t aoff = (ks>>2)*16384
                + SWZ(arow*128 + (ks&3)*32 + ((lane>>4)<<4));
            uint32_t qa[4], qla[4];
            ldsm4(QH + aoff, qa);
            ldsm4(QL + aoff, qla);

            const int krow0 = (lane & 7) + ((lane >> 4) << 3);
            const uint32_t kcol = (uint32_t)((ks&3)*32 + (((lane>>3)&1)<<4));
            #pragma unroll
            for (int ntp = 0; ntp < 4; ntp++) {
                const uint32_t koff = (ks>>2)*8192 + SWZ((ntp*16 + krow0)*128 + kcol);
                uint32_t kb4[4], klb4[4];
                ldsm4(KB + koff, kb4);
                ldsm4(KB + 16384 + koff, klb4);
                mma16816(s[2*ntp],   qa,  &kb4[0]);
                mma16816(s[2*ntp],   qa,  &klb4[0]);
                mma16816(s[2*ntp],   qla, &kb4[0]);
                mma16816(s[2*ntp+1], qa,  &kb4[2]);
                mma16816(s[2*ntp+1], qa,  &klb4[2]);
                mma16816(s[2*ntp+1], qla, &kb4[2]);
            }
        }

        if (kt >= 2*qt) {
            #pragma unroll
            for (int t = 0; t < 8; t++) {
                #pragma unroll
                for (int j = 0; j < 2; j++) {
                    const int n = kt*64 + t*8 + 2*(lane & 3) + j;
                    if (n > rg0)     s[t][j]   = -1e30f;
                    if (n > rg0 + 8) s[t][2+j] = -1e30f;
                }
            }
        }

        float rm0 = -1e30f, rm1 = -1e30f;
        #pragma unroll
        for (int t = 0; t < 8; t++) {
            rm0 = fmaxf(rm0, fmaxf(s[t][0], s[t][1]));
            rm1 = fmaxf(rm1, fmaxf(s[t][2], s[t][3]));
        }
        rm0 = fmaxf(rm0, __shfl_xor_sync(0xffffffffu, rm0, 1));
        rm0 = fmaxf(rm0, __shfl_xor_sync(0xffffffffu, rm0, 2));
        rm1 = fmaxf(rm1, __shfl_xor_sync(0xffffffffu, rm1, 1));
        rm1 = fmaxf(rm1, __shfl_xor_sync(0xffffffffu, rm1, 2));

        const float mn0 = fmaxf(mr0, rm0), mn1 = fmaxf(mr1, rm1);
        const float sf0 = __expf(mr0 - mn0), sf1 = __expf(mr1 - mn1);
        mr0 = mn0; mr1 = mn1;

        float rs0 = 0.f, rs1 = 0.f;
        #pragma unroll
        for (int t = 0; t < 8; t++) {
            s[t][0] = __expf(s[t][0] - mn0);
            s[t][1] = __expf(s[t][1] - mn0);
            s[t][2] = __expf(s[t][2] - mn1);
            s[t][3] = __expf(s[t][3] - mn1);
            rs0 += s[t][0] + s[t][1];
            rs1 += s[t][2] + s[t][3];
        }
        rs0 += __shfl_xor_sync(0xffffffffu, rs0, 1);
        rs0 += __shfl_xor_sync(0xffffffffu, rs0, 2);
        rs1 += __shfl_xor_sync(0xffffffffu, rs1, 1);
        rs1 += __shfl_xor_sync(0xffffffffu, rs1, 2);
        lr0 = lr0 * sf0 + rs0;
        lr1 = lr1 * sf1 + rs1;

        #pragma unroll
        for (int t = 0; t < 16; t++) {
            o[t][0] *= sf0; o[t][1] *= sf0;
            o[t][2] *= sf1; o[t][3] *= sf1;
        }

        uint32_t aph[4][4], apl[4][4];
        #pragma unroll
        for (int g = 0; g < 4; g++) {
            split2(s[2*g][0],   s[2*g][1],   aph[g][0], apl[g][0]);
            split2(s[2*g][2],   s[2*g][3],   aph[g][1], apl[g][1]);
            split2(s[2*g+1][0], s[2*g+1][1], aph[g][2], apl[g][2]);
            split2(s[2*g+1][2], s[2*g+1][3], aph[g][3], apl[g][3]);
        }

        const int vrow0 = (lane & 15);
        const uint32_t vcadd = (uint32_t)((lane >> 4) << 4);
        #pragma unroll
        for (int dtp = 0; dtp < 8; dtp++) {
            const uint32_t vcol = (uint32_t)((dtp&3)*32) + vcadd;
            #pragma unroll
            for (int g = 0; g < 4; g++) {
                const uint32_t voff = (dtp>>2)*8192 + SWZ((g*16 + vrow0)*128 + vcol);
                uint32_t vb4[4], vlb4[4];
                ldsm4t(VB + voff, vb4);
                ldsm4t(VB + 16384 + voff, vlb4);
                mma16816(o[2*dtp],   aph[g], &vb4[0]);
                mma16816(o[2*dtp],   aph[g], &vlb4[0]);
                mma16816(o[2*dtp],   apl[g], &vb4[0]);
                mma16816(o[2*dtp+1], aph[g], &vb4[2]);
                mma16816(o[2*dtp+1], aph[g], &vlb4[2]);
                mma16816(o[2*dtp+1], apl[g], &vb4[2]);
            }
        }
        __syncthreads();
    }

    const float inv0 = 1.f / lr0, inv1 = 1.f / lr1;
    const size_t row0 = ((size_t)(b*SEQ + rg0)) * D_MODEL + h*HDIM;
    const size_t row1 = row0 + 8 * D_MODEL;
    #pragma unroll
    for (int t = 0; t < 16; t++) {
        const int d = t*8 + 2*(lane & 3);
        uint32_t hi, lo;
        split2(o[t][0]*inv0, o[t][1]*inv0, hi, lo);
        *(uint32_t*)&g_ah[row0 + d] = hi;
        *(uint32_t*)&g_al[row0 + d] = lo;
        split2(o[t][2]*inv1, o[t][3]*inv1, hi, lo);
        *(uint32_t*)&g_ah[row1 + d] = hi;
        *(uint32_t*)&g_al[row1 + d] = lo;
    }
}

// ---------------------------------------------------------------------------
extern "C" void kernel_launch(void* const* d_in, const int* in_sizes, int n_in,
                              void* d_out, int out_size)
{
    const float* query = (const float*)d_in[0];
    const float* W_qkv = (const float*)d_in[1];
    const float* b_qkv = (const float*)d_in[2];
    const float* W_out = (const float*)d_in[3];
    const float* b_out = (const float*)d_in[4];
    float* out = (float*)d_out;

    void *p_qh, *p_ql, *p_wh, *p_wl, *p_oh, *p_ol, *p_ah, *p_al;
    cudaGetSymbolAddress(&p_qh, g_qh);  cudaGetSymbolAddress(&p_ql, g_ql);
    cudaGetSymbolAddress(&p_wh, g_wh);  cudaGetSymbolAddress(&p_wl, g_wl);
    cudaGetSymbolAddress(&p_oh, g_oh);  cudaGetSymbolAddress(&p_ol, g_ol);
    cudaGetSymbolAddress(&p_ah, g_ah);  cudaGetSymbolAddress(&p_al, g_al);

    const int GEMM_SMEM = 1024 + 2*65536;
    cudaFuncSetAttribute(tc_gemm<0>, cudaFuncAttributeMaxDynamicSharedMemorySize, GEMM_SMEM);
    cudaFuncSetAttribute(tc_gemm<1>, cudaFuncAttributeMaxDynamicSharedMemorySize, GEMM_SMEM);
    const int ATTN_SMEM = 1024 + 65536 + 2*65536;
    cudaFuncSetAttribute(attn_kernel, cudaFuncAttributeMaxDynamicSharedMemorySize, ATTN_SMEM);

    // 1) split inputs into bf16 hi/lo
    {
        int n;
        n = MROWS*D_MODEL;
        split_kernel<<<n/1024, 256>>>(query, (__nv_bfloat16*)p_qh, (__nv_bfloat16*)p_ql, n);
        n = 3*D_MODEL*D_MODEL;
        split_kernel<<<n/1024, 256>>>(W_qkv, (__nv_bfloat16*)p_wh, (__nv_bfloat16*)p_wl, n);
        n = D_MODEL*D_MODEL;
        split_kernel<<<n/1024, 256>>>(W_out, (__nv_bfloat16*)p_oh, (__nv_bfloat16*)p_ol, n);
    }

    // 2) QKV projection (HMMA): q,k fp32; v bf16 hi/lo
    tc_gemm<1><<<dim3(3*D_MODEL/128, MROWS/128), 256, GEMM_SMEM>>>(
        (const __nv_bfloat16*)p_qh, (const __nv_bfloat16*)p_ql,
        (const __nv_bfloat16*)p_wh, (const __nv_bfloat16*)p_wl,
        b_qkv, nullptr, 3*D_MODEL, D_MODEL);

    // 3) RoPE -> bf16 hi/lo Q,K
    rope_kernel<<<(BATCH*NHEAD*SEQ*64)/256, 256>>>();

    // 4) HMMA causal flash attention -> g_ah/g_al
    attn_kernel<<<dim3(SEQ/128, NHEAD, BATCH), 256, ATTN_SMEM>>>();

    // 5) Output projection (HMMA) -> d_out
    tc_gemm<0><<<dim3(D_MODEL/128, MROWS/128), 256, GEMM_SMEM>>>(
        (const __nv_bfloat16*)p_ah, (const __nv_bfloat16*)p_al,
        (const __nv_bfloat16*)p_oh, (const __nv_bfloat16*)p_ol,
        b_out, out, D_MODEL, D_MODEL);
}

// round 7
// speedup vs baseline: 4.1332x; 1.0091x over previous
#include <cuda_runtime.h>
#include <cuda_bf16.h>
#include <math.h>
#include <stdint.h>

#define D_MODEL 2048
#define NHEAD   16
#define HDIM    128
#define BATCH   2
#define SEQ     2048
#define MROWS   (BATCH*SEQ)   // 4096

// ---------------- device scratch (no runtime allocation) ----------------
__device__ float g_q[(size_t)BATCH*NHEAD*SEQ*HDIM];     // fp32 pre-rope Q
__device__ float g_k[(size_t)BATCH*NHEAD*SEQ*HDIM];     // fp32 pre-rope K

__device__ __nv_bfloat16 g_qbh[(size_t)BATCH*NHEAD*SEQ*HDIM];  // roped+scaled Q hi/lo
__device__ __nv_bfloat16 g_qbl[(size_t)BATCH*NHEAD*SEQ*HDIM];
__device__ __nv_bfloat16 g_kbh[(size_t)BATCH*NHEAD*SEQ*HDIM];  // roped K hi/lo
__device__ __nv_bfloat16 g_kbl[(size_t)BATCH*NHEAD*SEQ*HDIM];
__device__ __nv_bfloat16 g_vbh[(size_t)BATCH*NHEAD*SEQ*HDIM];  // V hi/lo
__device__ __nv_bfloat16 g_vbl[(size_t)BATCH*NHEAD*SEQ*HDIM];

__device__ __nv_bfloat16 g_qh[(size_t)MROWS*D_MODEL];       // query hi/lo (GEMM A)
__device__ __nv_bfloat16 g_ql[(size_t)MROWS*D_MODEL];
__device__ __nv_bfloat16 g_wh[(size_t)3*D_MODEL*D_MODEL];   // W_qkv hi/lo
__device__ __nv_bfloat16 g_wl[(size_t)3*D_MODEL*D_MODEL];
__device__ __nv_bfloat16 g_oh[(size_t)D_MODEL*D_MODEL];     // W_out hi/lo
__device__ __nv_bfloat16 g_ol[(size_t)D_MODEL*D_MODEL];
__device__ __nv_bfloat16 g_ah[(size_t)MROWS*D_MODEL];       // attn-out hi/lo
__device__ __nv_bfloat16 g_al[(size_t)MROWS*D_MODEL];

// ---------------- helpers ----------------
__device__ __forceinline__ uint32_t smem_u32(const void* p) {
    uint32_t a;
    asm("{ .reg .u64 t; cvta.to.shared.u64 t, %1; cvt.u32.u64 %0, t; }" : "=r"(a) : "l"(p));
    return a;
}
#define SWZ(o) ((o) ^ (((o) >> 3) & 0x70))

__device__ __forceinline__ void ldsm4(uint32_t addr, uint32_t* r) {
    asm volatile("ldmatrix.sync.aligned.m8n8.x4.shared.b16 {%0,%1,%2,%3}, [%4];"
                 : "=r"(r[0]), "=r"(r[1]), "=r"(r[2]), "=r"(r[3]) : "r"(addr));
}
__device__ __forceinline__ void ldsm4t(uint32_t addr, uint32_t* r) {
    asm volatile("ldmatrix.sync.aligned.m8n8.x4.trans.shared.b16 {%0,%1,%2,%3}, [%4];"
                 : "=r"(r[0]), "=r"(r[1]), "=r"(r[2]), "=r"(r[3]) : "r"(addr));
}
__device__ __forceinline__ void mma16816(float* c, const uint32_t* a, const uint32_t* b) {
    asm volatile(
        "mma.sync.aligned.m16n8k16.row.col.f32.bf16.bf16.f32 "
        "{%0,%1,%2,%3}, {%4,%5,%6,%7}, {%8,%9}, {%0,%1,%2,%3};"
        : "+f"(c[0]), "+f"(c[1]), "+f"(c[2]), "+f"(c[3])
        : "r"(a[0]), "r"(a[1]), "r"(a[2]), "r"(a[3]), "r"(b[0]), "r"(b[1]));
}
#define CP16(dst, src) \
    asm volatile("cp.async.cg.shared.global [%0], [%1], 16;" :: "r"(dst), "l"(src))
#define CP_COMMIT() asm volatile("cp.async.commit_group;" ::: "memory")
#define CP_WAIT0()  asm volatile("cp.async.wait_group 0;" ::: "memory")
#define CP_WAIT1()  asm volatile("cp.async.wait_group 1;" ::: "memory")

// split pair of fp32 into packed bf16x2 hi and lo (residual)
__device__ __forceinline__ void split2(float x, float y, uint32_t& hi, uint32_t& lo) {
    __nv_bfloat16 hx = __float2bfloat16(x), hy = __float2bfloat16(y);
    float rx = x - __bfloat162float(hx), ry = y - __bfloat162float(hy);
    __nv_bfloat16 lx = __float2bfloat16(rx), ly = __float2bfloat16(ry);
    hi = ((uint32_t)__bfloat16_as_ushort(hy) << 16) | __bfloat16_as_ushort(hx);
    lo = ((uint32_t)__bfloat16_as_ushort(ly) << 16) | __bfloat16_as_ushort(lx);
}

// ---------------------------------------------------------------------------
// fp32 -> bf16 hi/lo split
// ---------------------------------------------------------------------------
__global__ void split_kernel(const float* __restrict__ x,
                             __nv_bfloat16* __restrict__ hi,
                             __nv_bfloat16* __restrict__ lo, int n)
{
    int i = (blockIdx.x * 256 + threadIdx.x) * 4;
    if (i >= n) return;
    float4 v = *(const float4*)(x + i);
    uint32_t h0, l0, h1, l1;
    split2(v.x, v.y, h0, l0);
    split2(v.z, v.w, h1, l1);
    *(uint2*)(hi + i) = make_uint2(h0, h1);
    *(uint2*)(lo + i) = make_uint2(l0, l1);
}

// ---------------------------------------------------------------------------
// HMMA GEMM, 3-stage cp.async pipeline, ONE barrier per K-chunk
// (wait_group BEFORE __syncthreads -> cross-thread visibility).
// C = Ah*Bh^T + Ah*Bl^T + Al*Bh^T + bias   (fp32 accum)
// CTA 128x128, 8 warps, K-chunks of 64 bf16, SW128 smem (3 x 64KB buffers).
// MODE 0: write C fp32 row-major.
// MODE 1: QKV: q,k -> fp32 [B,H,L,128]; v -> bf16 hi/lo [B,H,L,128].
// ---------------------------------------------------------------------------
__device__ __forceinline__ void load_tiles_async(
    const __nv_bfloat16* __restrict__ a0, const __nv_bfloat16* __restrict__ a1,
    const __nv_bfloat16* __restrict__ b0, const __nv_bfloat16* __restrict__ b1,
    int K, uint32_t dst)
{
    const __nv_bfloat16* s[4] = {a0, a1, b0, b1};
    #pragma unroll
    for (int t = 0; t < 4; t++) {
        uint32_t d = dst + t * 16384;
        const __nv_bfloat16* p = s[t];
        #pragma unroll
        for (int it = 0; it < 4; it++) {
            int i = threadIdx.x + it * 256;        // 0..1023 (16B units)
            int r = i >> 3, c = i & 7;
            CP16(d + SWZ(r * 128 + c * 16), p + (size_t)r * K + c * 8);
        }
    }
}

template<int MODE>
__global__ __launch_bounds__(256, 1)
void tc_gemm(const __nv_bfloat16* __restrict__ Ah, const __nv_bfloat16* __restrict__ Al,
             const __nv_bfloat16* __restrict__ Bh, const __nv_bfloat16* __restrict__ Bl,
             const float* __restrict__ bias, float* __restrict__ C, int N, int K)
{
    extern __shared__ char smem[];
    const uint32_t bufs = (smem_u32(smem) + 1023) & ~1023u;

    const int tid  = threadIdx.x;
    const int lane = tid & 31;
    const int wid  = tid >> 5;
    const int wr   = wid >> 2;
    const int wc   = wid & 3;
    const int m0   = blockIdx.y << 7;
    const int n0   = blockIdx.x << 7;
    const int KCHUNKS = K >> 6;

    const __nv_bfloat16* Ahp = Ah + (size_t)m0 * K;
    const __nv_bfloat16* Alp = Al + (size_t)m0 * K;
    const __nv_bfloat16* Bhp = Bh + (size_t)n0 * K;
    const __nv_bfloat16* Blp = Bl + (size_t)n0 * K;

    float acc[4][4][4];
    #pragma unroll
    for (int i = 0; i < 4; i++)
        #pragma unroll
        for (int j = 0; j < 4; j++)
            #pragma unroll
            for (int r = 0; r < 4; r++) acc[i][j][r] = 0.f;

    const uint32_t sw   = (lane & 7) << 4;
    const int      arow = lane & 15;
    const uint32_t adk  = (lane >> 4) << 4;
    const int      brow = (lane & 7) + ((lane >> 4) << 3);
    const uint32_t bdk  = ((lane >> 3) & 1) << 4;

    uint32_t aro[4], bro[2];
    #pragma unroll
    for (int mt = 0; mt < 4; mt++) aro[mt] = (uint32_t)(wr*64 + mt*16 + arow) * 128;
    #pragma unroll
    for (int np = 0; np < 2; np++) bro[np] = (uint32_t)(wc*32 + np*16 + brow) * 128;

    // prologue: stage chunks 0 and 1; make chunk 0 visible
    load_tiles_async(Ahp, Alp, Bhp, Blp, K, bufs);
    CP_COMMIT();
    if (KCHUNKS > 1) {
        load_tiles_async(Ahp + 64, Alp + 64, Bhp + 64, Blp + 64, K, bufs + 65536);
        CP_COMMIT();
        CP_WAIT1();
    } else {
        CP_WAIT0();
    }
    __syncthreads();

    for (int c = 0; c < KCHUNKS; c++) {
        // Issue chunk c+2 into buffer (c+2)%3 == (c-1)%3. Safe: every thread
        // entering iteration c has passed the end-of-(c-1) barrier, so all
        // reads of that buffer are done.
        if (c + 2 < KCHUNKS) {
            const int k64 = (c + 2) << 6;
            load_tiles_async(Ahp + k64, Alp + k64, Bhp + k64, Blp + k64, K,
                             bufs + ((c + 2) % 3) * 65536);
            CP_COMMIT();
        }

        const uint32_t base = bufs + (c % 3) * 65536;
        const uint32_t bAh = base, bAl = base + 16384, bBh = base + 32768, bBl = base + 49152;

        #pragma unroll
        for (int ks = 0; ks < 4; ks++) {
            const uint32_t kb  = (uint32_t)ks * 32;
            const uint32_t kcA = (kb + adk) ^ sw;
            const uint32_t kcB = (kb + bdk) ^ sw;

            uint32_t ah[4][4], al[4][4], bhx[2][4], blx[2][4];
            #pragma unroll
            for (int mt = 0; mt < 4; mt++) {
                ldsm4(bAh + aro[mt] + kcA, ah[mt]);
                ldsm4(bAl + aro[mt] + kcA, al[mt]);
            }
            #pragma unroll
            for (int np = 0; np < 2; np++) {
                ldsm4(bBh + bro[np] + kcB, bhx[np]);
                ldsm4(bBl + bro[np] + kcB, blx[np]);
            }
            #pragma unroll
            for (int mt = 0; mt < 4; mt++)
                #pragma unroll
                for (int nt = 0; nt < 4; nt++) {
                    const uint32_t* bh2 = &bhx[nt >> 1][(nt & 1) * 2];
                    const uint32_t* bl2 = &blx[nt >> 1][(nt & 1) * 2];
                    mma16816(acc[mt][nt], ah[mt], bh2);
                    mma16816(acc[mt][nt], ah[mt], bl2);
                    mma16816(acc[mt][nt], al[mt], bh2);
                }
        }

        // make chunk c+1 visible to ALL threads: own-wait THEN barrier
        if (c + 1 < KCHUNKS) {
            if (c + 2 < KCHUNKS) CP_WAIT1(); else CP_WAIT0();
            __syncthreads();
        }
    }

    // epilogue
    const int which = n0 >> 11;
    const int h     = (n0 >> 7) & 15;

    #pragma unroll
    for (int mt = 0; mt < 4; mt++) {
        const int mrow = m0 + wr*64 + mt*16 + (lane >> 2);
        #pragma unroll
        for (int nt = 0; nt < 4; nt++) {
            const int cl = wc*32 + nt*8 + (lane & 3)*2;
            const int cg = n0 + cl;
            const float bx = bias[cg], by = bias[cg + 1];
            float2 v0 = make_float2(acc[mt][nt][0] + bx, acc[mt][nt][1] + by);
            float2 v1 = make_float2(acc[mt][nt][2] + bx, acc[mt][nt][3] + by);
            if (MODE == 1) {
                const int b0r = mrow >> 11, l0r = mrow & (SEQ - 1);
                const int m1  = mrow + 8;
                const int b1r = m1 >> 11,   l1r = m1 & (SEQ - 1);
                const size_t i0 = (((size_t)(b0r*NHEAD + h))*SEQ + l0r)*HDIM + cl;
                const size_t i1 = (((size_t)(b1r*NHEAD + h))*SEQ + l1r)*HDIM + cl;
                if (which == 2) {
                    uint32_t hi, lo;
                    split2(v0.x, v0.y, hi, lo);
                    *(uint32_t*)&g_vbh[i0] = hi; *(uint32_t*)&g_vbl[i0] = lo;
                    split2(v1.x, v1.y, hi, lo);
                    *(uint32_t*)&g_vbh[i1] = hi; *(uint32_t*)&g_vbl[i1] = lo;
                } else {
                    float* qk = (which == 0) ? g_q : g_k;
                    *(float2*)&qk[i0] = v0;
                    *(float2*)&qk[i1] = v1;
                }
            } else {
                *(float2*)&C[(size_t)mrow * N + cg]       = v0;
                *(float2*)&C[(size_t)(mrow + 8) * N + cg] = v1;
            }
        }
    }
}

// ---------------------------------------------------------------------------
// RoPE: reads fp32 g_q/g_k, writes bf16 hi/lo (Q scaled by 1/sqrt(128)).
// ---------------------------------------------------------------------------
__global__ void rope_kernel()
{
    const int total = BATCH*NHEAD*SEQ*64;
    int idx = blockIdx.x * blockDim.x + threadIdx.x;
    if (idx >= total) return;
    const int d    = idx & 63;
    const int rowi = idx >> 6;
    const int l    = rowi & (SEQ - 1);

    double invf = exp2(-(double)d * (13.287712379549449 / 64.0)); // 10000^(-d/64)
    double t    = fmod((double)l * invf, 6.283185307179586476925286766559);
    float c = cosf((float)t);
    float s = sinf((float)t);

    const size_t base = (size_t)rowi * HDIM;
    const float qs = 0.08838834764831845f;

    float q1 = g_q[base + d], q2 = g_q[base + d + 64];
    float k1 = g_k[base + d], k2 = g_k[base + d + 64];
    float qo1 = (q1*c - q2*s) * qs, qo2 = (q2*c + q1*s) * qs;
    float ko1 = k1*c - k2*s,       ko2 = k2*c + k1*s;

    __nv_bfloat16 h;
    h = __float2bfloat16(qo1); g_qbh[base+d]    = h; g_qbl[base+d]    = __float2bfloat16(qo1 - __bfloat162float(h));
    h = __float2bfloat16(qo2); g_qbh[base+d+64] = h; g_qbl[base+d+64] = __float2bfloat16(qo2 - __bfloat162float(h));
    h = __float2bfloat16(ko1); g_kbh[base+d]    = h; g_kbl[base+d]    = __float2bfloat16(ko1 - __bfloat162float(h));
    h = __float2bfloat16(ko2); g_kbh[base+d+64] = h; g_kbl[base+d+64] = __float2bfloat16(ko2 - __bfloat162float(h));
}

// ---------------------------------------------------------------------------
// HMMA causal flash attention. BQ=128, BK=64, 8 warps (16 q-rows each).
// Double-buffered KV, ONE barrier per KV block (wait THEN sync).
// ---------------------------------------------------------------------------
__global__ __launch_bounds__(256, 1)
void attn_kernel()
{
    extern __shared__ char sm[];
    const uint32_t base = (smem_u32(sm) + 1023) & ~1023u;
    const uint32_t QH = base;                 // 2 panels x 16KB (dims 0-63, 64-127)
    const uint32_t QL = base + 32768;
    const uint32_t KV = base + 65536;         // buf b: +b*65536: Kh,Kl,Vh,Vl (16KB each)

    const int tid  = threadIdx.x;
    const int lane = tid & 31;
    const int wid  = tid >> 5;
    const int qt   = (int)gridDim.x - 1 - (int)blockIdx.x;  // heavy tiles first
    const int h    = blockIdx.y;
    const int b    = blockIdx.z;
    const int bh   = b*NHEAD + h;
    const int q0   = qt << 7;
    const int nkv  = 2*qt + 2;

    const size_t hoff = (size_t)bh * SEQ * HDIM;
    const __nv_bfloat16* qbh = g_qbh + hoff + (size_t)q0 * HDIM;
    const __nv_bfloat16* qbl = g_qbl + hoff + (size_t)q0 * HDIM;
    const __nv_bfloat16* kbh = g_kbh + hoff;
    const __nv_bfloat16* kbl = g_kbl + hoff;
    const __nv_bfloat16* vbh = g_vbh + hoff;
    const __nv_bfloat16* vbl = g_vbl + hoff;

    #pragma unroll
    for (int it = 0; it < 8; it++) {
        int i = tid + it * 256;
        int row = i >> 4, u = i & 15;
        uint32_t off = (u >> 3) * 16384 + SWZ(row * 128 + (u & 7) * 16);
        CP16(QH + off, qbh + (size_t)row * HDIM + u * 8);
        CP16(QL + off, qbl + (size_t)row * HDIM + u * 8);
    }
    {
        const __nv_bfloat16* arr[4] = {kbh, kbl, vbh, vbl};
        #pragma unroll
        for (int t = 0; t < 4; t++)
            #pragma unroll
            for (int it = 0; it < 4; it++) {
                int i = tid + it * 256;
                int row = i >> 4, u = i & 15;
                uint32_t d = KV + t*16384 + (u>>3)*8192 + SWZ(row*128 + (u&7)*16);
                CP16(d, arr[t] + (size_t)row * HDIM + u * 8);
            }
    }
    CP_COMMIT();
    CP_WAIT0();
    __syncthreads();

    float mr0 = -1e30f, mr1 = -1e30f, lr0 = 0.f, lr1 = 0.f;
    float o[16][4];
    #pragma unroll
    for (int t = 0; t < 16; t++)
        #pragma unroll
        for (int j = 0; j < 4; j++) o[t][j] = 0.f;

    const int rloc0 = wid*16 + (lane >> 2);
    const int rg0   = q0 + rloc0;

    for (int kt = 0; kt < nkv; kt++) {
        const uint32_t KB = KV + (kt & 1) * 65536;
        const uint32_t VB = KB + 32768;

        // Issue KV(kt+1) into the other buffer. Safe: all threads passed the
        // end-of-(kt-1) barrier, so reads of that buffer are complete.
        if (kt + 1 < nkv) {
            const __nv_bfloat16* arr[4] = {kbh, kbl, vbh, vbl};
            const size_t s0 = (size_t)(kt + 1) * 64 * HDIM;
            const uint32_t nb = KV + ((kt + 1) & 1) * 65536;
            #pragma unroll
            for (int t = 0; t < 4; t++)
                #pragma unroll
                for (int it = 0; it < 4; it++) {
                    int i = tid + it * 256;
                    int row = i >> 4, u = i & 15;
                    uint32_t d = nb + t*16384 + (u>>3)*8192 + SWZ(row*128 + (u&7)*16);
                    CP16(d, arr[t] + s0 + (size_t)row * HDIM + u * 8);
                }
            CP_COMMIT();
        }

        float s[8][4];
        #pragma unroll
        for (int t = 0; t < 8; t++)
            #pragma unroll
            for (int j = 0; j < 4; j++) s[t][j] = 0.f;

        #pragma unroll
        for (int ks = 0; ks < 8; ks++) {
            const int arow = wid*16 + (lane & 15);
            const uint32_t aoff = (ks>>2)*16384
                + SWZ(arow*128 + (ks&3)*32 + ((lane>>4)<<4));
            uint32_t qa[4], qla[4];
            ldsm4(QH + aoff, qa);
            ldsm4(QL + aoff, qla);

            const int krow0 = (lane & 7) + ((lane >> 4) << 3);
            const uint32_t kcol = (uint32_t)((ks&3)*32 + (((lane>>3)&1)<<4));
            #pragma unroll
            for (int ntp = 0; ntp < 4; ntp++) {
                const uint32_t koff = (ks>>2)*8192 + SWZ((ntp*16 + krow0)*128 + kcol);
                uint32_t kb4[4], klb4[4];
                ldsm4(KB + koff, kb4);
                ldsm4(KB + 16384 + koff, klb4);
                mma16816(s[2*ntp],   qa,  &kb4[0]);
                mma16816(s[2*ntp],   qa,  &klb4[0]);
                mma16816(s[2*ntp],   qla, &kb4[0]);
                mma16816(s[2*ntp+1], qa,  &kb4[2]);
                mma16816(s[2*ntp+1], qa,  &klb4[2]);
                mma16816(s[2*ntp+1], qla, &kb4[2]);
            }
        }

        if (kt >= 2*qt) {
            #pragma unroll
            for (int t = 0; t < 8; t++) {
                #pragma unroll
                for (int j = 0; j < 2; j++) {
                    const int n = kt*64 + t*8 + 2*(lane & 3) + j;
                    if (n > rg0)     s[t][j]   = -1e30f;
                    if (n > rg0 + 8) s[t][2+j] = -1e30f;
                }
            }
        }

        float rm0 = -1e30f, rm1 = -1e30f;
        #pragma unroll
        for (int t = 0; t < 8; t++) {
            rm0 = fmaxf(rm0, fmaxf(s[t][0], s[t][1]));
            rm1 = fmaxf(rm1, fmaxf(s[t][2], s[t][3]));
        }
        rm0 = fmaxf(rm0, __shfl_xor_sync(0xffffffffu, rm0, 1));
        rm0 = fmaxf(rm0, __shfl_xor_sync(0xffffffffu, rm0, 2));
        rm1 = fmaxf(rm1, __shfl_xor_sync(0xffffffffu, rm1, 1));
        rm1 = fmaxf(rm1, __shfl_xor_sync(0xffffffffu, rm1, 2));

        const float mn0 = fmaxf(mr0, rm0), mn1 = fmaxf(mr1, rm1);
        const float sf0 = __expf(mr0 - mn0), sf1 = __expf(mr1 - mn1);
        mr0 = mn0; mr1 = mn1;

        float rs0 = 0.f, rs1 = 0.f;
        #pragma unroll
        for (int t = 0; t < 8; t++) {
            s[t][0] = __expf(s[t][0] - mn0);
            s[t][1] = __expf(s[t][1] - mn0);
            s[t][2] = __expf(s[t][2] - mn1);
            s[t][3] = __expf(s[t][3] - mn1);
            rs0 += s[t][0] + s[t][1];
            rs1 += s[t][2] + s[t][3];
        }
        rs0 += __shfl_xor_sync(0xffffffffu, rs0, 1);
        rs0 += __shfl_xor_sync(0xffffffffu, rs0, 2);
        rs1 += __shfl_xor_sync(0xffffffffu, rs1, 1);
        rs1 += __shfl_xor_sync(0xffffffffu, rs1, 2);
        lr0 = lr0 * sf0 + rs0;
        lr1 = lr1 * sf1 + rs1;

        #pragma unroll
        for (int t = 0; t < 16; t++) {
            o[t][0] *= sf0; o[t][1] *= sf0;
            o[t][2] *= sf1; o[t][3] *= sf1;
        }

        uint32_t aph[4][4], apl[4][4];
        #pragma unroll
        for (int g = 0; g < 4; g++) {
            split2(s[2*g][0],   s[2*g][1],   aph[g][0], apl[g][0]);
            split2(s[2*g][2],   s[2*g][3],   aph[g][1], apl[g][1]);
            split2(s[2*g+1][0], s[2*g+1][1], aph[g][2], apl[g][2]);
            split2(s[2*g+1][2], s[2*g+1][3], aph[g][3], apl[g][3]);
        }

        const int vrow0 = (lane & 15);
        const uint32_t vcadd = (uint32_t)((lane >> 4) << 4);
        #pragma unroll
        for (int dtp = 0; dtp < 8; dtp++) {
            const uint32_t vcol = (uint32_t)((dtp&3)*32) + vcadd;
            #pragma unroll
            for (int g = 0; g < 4; g++) {
                const uint32_t voff = (dtp>>2)*8192 + SWZ((g*16 + vrow0)*128 + vcol);
                uint32_t vb4[4], vlb4[4];
                ldsm4t(VB + voff, vb4);
                ldsm4t(VB + 16384 + voff, vlb4);
                mma16816(o[2*dtp],   aph[g], &vb4[0]);
                mma16816(o[2*dtp],   aph[g], &vlb4[0]);
                mma16816(o[2*dtp],   apl[g], &vb4[0]);
                mma16816(o[2*dtp+1], aph[g], &vb4[2]);
                mma16816(o[2*dtp+1], aph[g], &vlb4[2]);
                mma16816(o[2*dtp+1], apl[g], &vb4[2]);
            }
        }

        // make KV(kt+1) visible: own-wait THEN barrier
        if (kt + 1 < nkv) {
            CP_WAIT0();
            __syncthreads();
        }
    }

    const float inv0 = 1.f / lr0, inv1 = 1.f / lr1;
    const size_t row0 = ((size_t)(b*SEQ + rg0)) * D_MODEL + h*HDIM;
    const size_t row1 = row0 + 8 * D_MODEL;
    #pragma unroll
    for (int t = 0; t < 16; t++) {
        const int d = t*8 + 2*(lane & 3);
        uint32_t hi, lo;
        split2(o[t][0]*inv0, o[t][1]*inv0, hi, lo);
        *(uint32_t*)&g_ah[row0 + d] = hi;
        *(uint32_t*)&g_al[row0 + d] = lo;
        split2(o[t][2]*inv1, o[t][3]*inv1, hi, lo);
        *(uint32_t*)&g_ah[row1 + d] = hi;
        *(uint32_t*)&g_al[row1 + d] = lo;
    }
}

// ---------------------------------------------------------------------------
extern "C" void kernel_launch(void* const* d_in, const int* in_sizes, int n_in,
                              void* d_out, int out_size)
{
    const float* query = (const float*)d_in[0];
    const float* W_qkv = (const float*)d_in[1];
    const float* b_qkv = (const float*)d_in[2];
    const float* W_out = (const float*)d_in[3];
    const float* b_out = (const float*)d_in[4];
    float* out = (float*)d_out;

    void *p_qh, *p_ql, *p_wh, *p_wl, *p_oh, *p_ol, *p_ah, *p_al;
    cudaGetSymbolAddress(&p_qh, g_qh);  cudaGetSymbolAddress(&p_ql, g_ql);
    cudaGetSymbolAddress(&p_wh, g_wh);  cudaGetSymbolAddress(&p_wl, g_wl);
    cudaGetSymbolAddress(&p_oh, g_oh);  cudaGetSymbolAddress(&p_ol, g_ol);
    cudaGetSymbolAddress(&p_ah, g_ah);  cudaGetSymbolAddress(&p_al, g_al);

    const int GEMM_SMEM = 1024 + 3*65536;       // 3-stage pipeline
    cudaFuncSetAttribute(tc_gemm<0>, cudaFuncAttributeMaxDynamicSharedMemorySize, GEMM_SMEM);
    cudaFuncSetAttribute(tc_gemm<1>, cudaFuncAttributeMaxDynamicSharedMemorySize, GEMM_SMEM);
    const int ATTN_SMEM = 1024 + 65536 + 2*65536;
    cudaFuncSetAttribute(attn_kernel, cudaFuncAttributeMaxDynamicSharedMemorySize, ATTN_SMEM);

    // 1) split inputs into bf16 hi/lo
    {
        int n;
        n = MROWS*D_MODEL;
        split_kernel<<<n/1024, 256>>>(query, (__nv_bfloat16*)p_qh, (__nv_bfloat16*)p_ql, n);
        n = 3*D_MODEL*D_MODEL;
        split_kernel<<<n/1024, 256>>>(W_qkv, (__nv_bfloat16*)p_wh, (__nv_bfloat16*)p_wl, n);
        n = D_MODEL*D_MODEL;
        split_kernel<<<n/1024, 256>>>(W_out, (__nv_bfloat16*)p_oh, (__nv_bfloat16*)p_ol, n);
    }

    // 2) QKV projection (HMMA): q,k fp32; v bf16 hi/lo
    tc_gemm<1><<<dim3(3*D_MODEL/128, MROWS/128), 256, GEMM_SMEM>>>(
        (const __nv_bfloat16*)p_qh, (const __nv_bfloat16*)p_ql,
        (const __nv_bfloat16*)p_wh, (const __nv_bfloat16*)p_wl,
        b_qkv, nullptr, 3*D_MODEL, D_MODEL);

    // 3) RoPE -> bf16 hi/lo Q,K
    rope_kernel<<<(BATCH*NHEAD*SEQ*64)/256, 256>>>();

    // 4) HMMA causal flash attention -> g_ah/g_al
    attn_kernel<<<dim3(SEQ/128, NHEAD, BATCH), 256, ATTN_SMEM>>>();

    // 5) Output projection (HMMA) -> d_out
    tc_gemm<0><<<dim3(D_MODEL/128, MROWS/128), 256, GEMM_SMEM>>>(
        (const __nv_bfloat16*)p_ah, (const __nv_bfloat16*)p_al,
        (const __nv_bfloat16*)p_oh, (const __nv_bfloat16*)p_ol,
        b_out, out, D_MODEL, D_MODEL);
}

// round 9
// speedup vs baseline: 4.4125x; 1.0676x over previous
#include <cuda_runtime.h>
#include <cuda_bf16.h>
#include <math.h>
#include <stdint.h>

#define D_MODEL 2048
#define NHEAD   16
#define HDIM    128
#define BATCH   2
#define SEQ     2048
#define MROWS   (BATCH*SEQ)   // 4096

// ---------------- device scratch (no runtime allocation) ----------------
__device__ __nv_bfloat16 g_qbh[(size_t)BATCH*NHEAD*SEQ*HDIM];  // roped+scaled Q hi/lo
__device__ __nv_bfloat16 g_qbl[(size_t)BATCH*NHEAD*SEQ*HDIM];
__device__ __nv_bfloat16 g_kbh[(size_t)BATCH*NHEAD*SEQ*HDIM];  // roped K hi/lo
__device__ __nv_bfloat16 g_kbl[(size_t)BATCH*NHEAD*SEQ*HDIM];
__device__ __nv_bfloat16 g_vbh[(size_t)BATCH*NHEAD*SEQ*HDIM];  // V hi/lo
__device__ __nv_bfloat16 g_vbl[(size_t)BATCH*NHEAD*SEQ*HDIM];

__device__ __nv_bfloat16 g_qh[(size_t)MROWS*D_MODEL];       // query hi/lo (GEMM A)
__device__ __nv_bfloat16 g_ql[(size_t)MROWS*D_MODEL];
__device__ __nv_bfloat16 g_wh[(size_t)3*D_MODEL*D_MODEL];   // W_qkv hi/lo
__device__ __nv_bfloat16 g_wl[(size_t)3*D_MODEL*D_MODEL];
__device__ __nv_bfloat16 g_oh[(size_t)D_MODEL*D_MODEL];     // W_out hi/lo
__device__ __nv_bfloat16 g_ol[(size_t)D_MODEL*D_MODEL];
__device__ __nv_bfloat16 g_ah[(size_t)MROWS*D_MODEL];       // attn-out hi/lo
__device__ __nv_bfloat16 g_al[(size_t)MROWS*D_MODEL];

__device__ float g_cos[(size_t)SEQ*64];                     // rope tables
__device__ float g_sin[(size_t)SEQ*64];

// ---------------- helpers ----------------
__device__ __forceinline__ uint32_t smem_u32(const void* p) {
    uint32_t a;
    asm("{ .reg .u64 t; cvta.to.shared.u64 t, %1; cvt.u32.u64 %0, t; }" : "=r"(a) : "l"(p));
    return a;
}
#define SWZ(o) ((o) ^ (((o) >> 3) & 0x70))

__device__ __forceinline__ void ldsm4(uint32_t addr, uint32_t* r) {
    asm volatile("ldmatrix.sync.aligned.m8n8.x4.shared.b16 {%0,%1,%2,%3}, [%4];"
                 : "=r"(r[0]), "=r"(r[1]), "=r"(r[2]), "=r"(r[3]) : "r"(addr));
}
__device__ __forceinline__ void ldsm4t(uint32_t addr, uint32_t* r) {
    asm volatile("ldmatrix.sync.aligned.m8n8.x4.trans.shared.b16 {%0,%1,%2,%3}, [%4];"
                 : "=r"(r[0]), "=r"(r[1]), "=r"(r[2]), "=r"(r[3]) : "r"(addr));
}
__device__ __forceinline__ void mma16816(float* c, const uint32_t* a, const uint32_t* b) {
    asm volatile(
        "mma.sync.aligned.m16n8k16.row.col.f32.bf16.bf16.f32 "
        "{%0,%1,%2,%3}, {%4,%5,%6,%7}, {%8,%9}, {%0,%1,%2,%3};"
        : "+f"(c[0]), "+f"(c[1]), "+f"(c[2]), "+f"(c[3])
        : "r"(a[0]), "r"(a[1]), "r"(a[2]), "r"(a[3]), "r"(b[0]), "r"(b[1]));
}
#define CP16(dst, src) \
    asm volatile("cp.async.cg.shared.global [%0], [%1], 16;" :: "r"(dst), "l"(src))
#define CP_COMMIT() asm volatile("cp.async.commit_group;" ::: "memory")
#define CP_WAIT0()  asm volatile("cp.async.wait_group 0;" ::: "memory")
#define CP_WAIT1()  asm volatile("cp.async.wait_group 1;" ::: "memory")

// split pair of fp32 into packed bf16x2 hi and lo (residual)
__device__ __forceinline__ void split2(float x, float y, uint32_t& hi, uint32_t& lo) {
    __nv_bfloat16 hx = __float2bfloat16(x), hy = __float2bfloat16(y);
    float rx = x - __bfloat162float(hx), ry = y - __bfloat162float(hy);
    __nv_bfloat16 lx = __float2bfloat16(rx), ly = __float2bfloat16(ry);
    hi = ((uint32_t)__bfloat16_as_ushort(hy) << 16) | __bfloat16_as_ushort(hx);
    lo = ((uint32_t)__bfloat16_as_ushort(ly) << 16) | __bfloat16_as_ushort(lx);
}

// ---------------------------------------------------------------------------
// fp32 -> bf16 hi/lo split
// ---------------------------------------------------------------------------
__global__ void split_kernel(const float* __restrict__ x,
                             __nv_bfloat16* __restrict__ hi,
                             __nv_bfloat16* __restrict__ lo, int n)
{
    int i = (blockIdx.x * 256 + threadIdx.x) * 4;
    if (i >= n) return;
    float4 v = *(const float4*)(x + i);
    uint32_t h0, l0, h1, l1;
    split2(v.x, v.y, h0, l0);
    split2(v.z, v.w, h1, l1);
    *(uint2*)(hi + i) = make_uint2(h0, h1);
    *(uint2*)(lo + i) = make_uint2(l0, l1);
}

// ---------------------------------------------------------------------------
// RoPE cos/sin table (double-precision range reduction, robust to fast-math)
// ---------------------------------------------------------------------------
__global__ void rope_table_kernel()
{
    int idx = blockIdx.x * 256 + threadIdx.x;       // SEQ*64 threads
    int l = idx >> 6, d = idx & 63;
    double invf = exp2(-(double)d * (13.287712379549449 / 64.0)); // 10000^(-d/64)
    double t    = fmod((double)l * invf, 6.283185307179586476925286766559);
    g_cos[idx] = cosf((float)t);
    g_sin[idx] = sinf((float)t);
}

// ---------------------------------------------------------------------------
// HMMA GEMM, 3-stage cp.async pipeline, K-chunks of 32 (32KB each, packed:
// 128B smem row = [hi 64B | lo 64B]). 2 CTAs/SM.
// C = Ah*Bh^T + Ah*Bl^T + Al*Bh^T + bias   (fp32 accum)
// MODE 0: write C fp32 row-major.
// MODE 1: QKV epilogue with fused RoPE: q,k -> roped bf16 hi/lo [B,H,L,128]
//         (q scaled 1/sqrt(128)); v -> bf16 hi/lo.
// ---------------------------------------------------------------------------
__device__ __forceinline__ void load_chunk_async(
    const __nv_bfloat16* __restrict__ a0, const __nv_bfloat16* __restrict__ a1,
    const __nv_bfloat16* __restrict__ b0, const __nv_bfloat16* __restrict__ b1,
    int K, int k0, uint32_t dst)
{
    const __nv_bfloat16* s[4] = {a0, a1, b0, b1};
    #pragma unroll
    for (int t = 0; t < 4; t++) {
        const __nv_bfloat16* p = s[t] + k0;
        const uint32_t d = dst + (t >> 1) * 16384;
        #pragma unroll
        for (int it = 0; it < 2; it++) {
            int i = threadIdx.x + it * 256;     // 0..511 (16B units per array)
            int r = i >> 2, c = i & 3;
            CP16(d + SWZ(r * 128 + (t & 1) * 64 + c * 16),
                 p + (size_t)r * K + c * 8);
        }
    }
}

template<int MODE>
__global__ __launch_bounds__(256, 2)
void tc_gemm(const __nv_bfloat16* __restrict__ Ah, const __nv_bfloat16* __restrict__ Al,
             const __nv_bfloat16* __restrict__ Bh, const __nv_bfloat16* __restrict__ Bl,
             const float* __restrict__ bias, float* __restrict__ C, int N, int K)
{
    extern __shared__ char smem[];
    char* smp = (char*)(((uintptr_t)smem + 1023) & ~(uintptr_t)1023);
    const uint32_t bufs = smem_u32(smp);

    const int tid  = threadIdx.x;
    const int lane = tid & 31;
    const int wid  = tid >> 5;
    const int wr   = wid >> 2;
    const int wc   = wid & 3;
    const int m0   = blockIdx.y << 7;
    const int n0   = blockIdx.x << 7;
    const int KCHUNKS = K >> 5;

    const __nv_bfloat16* Ahp = Ah + (size_t)m0 * K;
    const __nv_bfloat16* Alp = Al + (size_t)m0 * K;
    const __nv_bfloat16* Bhp = Bh + (size_t)n0 * K;
    const __nv_bfloat16* Blp = Bl + (size_t)n0 * K;

    float acc[4][4][4];
    #pragma unroll
    for (int i = 0; i < 4; i++)
        #pragma unroll
        for (int j = 0; j < 4; j++)
            #pragma unroll
            for (int r = 0; r < 4; r++) acc[i][j][r] = 0.f;

    const int      arow = lane & 15;
    const uint32_t adk  = (lane >> 4) << 4;
    const int      brow = (lane & 7) + ((lane >> 4) << 3);
    const uint32_t bdk  = ((lane >> 3) & 1) << 4;

    // prologue: stage chunks 0,1; make chunk 0 visible
    load_chunk_async(Ahp, Alp, Bhp, Blp, K, 0,  bufs);
    CP_COMMIT();
    load_chunk_async(Ahp, Alp, Bhp, Blp, K, 32, bufs + 32768);
    CP_COMMIT();
    CP_WAIT1();
    __syncthreads();

    for (int c = 0; c < KCHUNKS; c++) {
        if (c + 2 < KCHUNKS) {
            load_chunk_async(Ahp, Alp, Bhp, Blp, K, (c + 2) << 5,
                             bufs + ((c + 2) % 3) * 32768);
            CP_COMMIT();
        }

        const uint32_t bA = bufs + (c % 3) * 32768;
        const uint32_t bB = bA + 16384;

        #pragma unroll
        for (int ks = 0; ks < 2; ks++) {
            const uint32_t kbA = (uint32_t)ks * 32 + adk;
            const uint32_t kbB = (uint32_t)ks * 32 + bdk;

            uint32_t ah[4][4], bh[2][4], bl[2][4];
            #pragma unroll
            for (int mt = 0; mt < 4; mt++)
                ldsm4(bA + SWZ((uint32_t)(wr*64 + mt*16 + arow) * 128 + kbA), ah[mt]);
            #pragma unroll
            for (int np = 0; np < 2; np++) {
                const uint32_t rw = (uint32_t)(wc*32 + np*16 + brow) * 128;
                ldsm4(bB + SWZ(rw + kbB), bh[np]);
                ldsm4(bB + SWZ(rw + 64 + kbB), bl[np]);
            }
            #pragma unroll
            for (int mt = 0; mt < 4; mt++)
                #pragma unroll
                for (int nt = 0; nt < 4; nt++) {
                    mma16816(acc[mt][nt], ah[mt], &bh[nt >> 1][(nt & 1) * 2]);
                    mma16816(acc[mt][nt], ah[mt], &bl[nt >> 1][(nt & 1) * 2]);
                }
            uint32_t al[4][4];
            #pragma unroll
            for (int mt = 0; mt < 4; mt++)
                ldsm4(bA + SWZ((uint32_t)(wr*64 + mt*16 + arow) * 128 + 64 + kbA), al[mt]);
            #pragma unroll
            for (int mt = 0; mt < 4; mt++)
                #pragma unroll
                for (int nt = 0; nt < 4; nt++)
                    mma16816(acc[mt][nt], al[mt], &bh[nt >> 1][(nt & 1) * 2]);
        }

        if (c + 1 < KCHUNKS) {
            if (c + 2 < KCHUNKS) CP_WAIT1(); else CP_WAIT0();
            __syncthreads();
        }
    }

    if (MODE == 0) {
        #pragma unroll
        for (int mt = 0; mt < 4; mt++) {
            const int mrow = m0 + wr*64 + mt*16 + (lane >> 2);
            #pragma unroll
            for (int nt = 0; nt < 4; nt++) {
                const int cg = n0 + wc*32 + nt*8 + (lane & 3)*2;
                const float bx = bias[cg], by = bias[cg + 1];
                *(float2*)&C[(size_t)mrow * N + cg] =
                    make_float2(acc[mt][nt][0] + bx, acc[mt][nt][1] + by);
                *(float2*)&C[(size_t)(mrow + 8) * N + cg] =
                    make_float2(acc[mt][nt][2] + bx, acc[mt][nt][3] + by);
            }
        }
        return;
    }

    // ---------------- MODE 1 epilogue: stage -> rope/split -> scatter -------
    float* st = (float*)smp;                 // 128 x 132 fp32 (67.6KB <= bufs)
    const int PITCH = 132;
    __syncthreads();                          // all buffer reads done
    #pragma unroll
    for (int mt = 0; mt < 4; mt++) {
        const int r0 = wr*64 + mt*16 + (lane >> 2);
        #pragma unroll
        for (int nt = 0; nt < 4; nt++) {
            const int cl = wc*32 + nt*8 + (lane & 3)*2;
            const float bx = bias[n0 + cl], by = bias[n0 + cl + 1];
            *(float2*)&st[r0*PITCH + cl] =
                make_float2(acc[mt][nt][0] + bx, acc[mt][nt][1] + by);
            *(float2*)&st[(r0 + 8)*PITCH + cl] =
                make_float2(acc[mt][nt][2] + bx, acc[mt][nt][3] + by);
        }
    }
    __syncthreads();

    const int which = n0 >> 11;              // 0=q 1=k 2=v
    const int h     = (n0 >> 7) & 15;
    const int row   = tid >> 1;
    const int half  = tid & 1;
    const int m     = m0 + row;
    const int bb    = m >> 11;
    const int l     = m & (SEQ - 1);
    const size_t obase = (((size_t)(bb*NHEAD + h))*SEQ + l)*HDIM;
    const float* srow = st + row * PITCH;

    if (which == 2) {
        // Each thread covers dims [d0, d0+32) AND [d0+64, d0+96), d0 = half*32
        // (same coverage pattern as q/k: two threads per row -> all 128 dims).
        const int d0 = half * 32;
        uint32_t h1[16], l1[16], h2[16], l2[16];
        #pragma unroll
        for (int j = 0; j < 16; j++) {
            split2(srow[d0 + 2*j],      srow[d0 + 2*j + 1],      h1[j], l1[j]);
            split2(srow[d0 + 64 + 2*j], srow[d0 + 64 + 2*j + 1], h2[j], l2[j]);
        }
        #pragma unroll
        for (int j = 0; j < 4; j++) {
            *(uint4*)&g_vbh[obase + d0 + j*8]      = ((uint4*)h1)[j];
            *(uint4*)&g_vbl[obase + d0 + j*8]      = ((uint4*)l1)[j];
            *(uint4*)&g_vbh[obase + d0 + 64 + j*8] = ((uint4*)h2)[j];
            *(uint4*)&g_vbl[obase + d0 + 64 + j*8] = ((uint4*)l2)[j];
        }
    } else {
        const float qs = (which == 0) ? 0.08838834764831845f : 1.0f;
        const int d0 = half * 32;
        const float* ct = g_cos + (size_t)l * 64;
        const float* stb = g_sin + (size_t)l * 64;
        uint32_t h1[16], l1[16], h2[16], l2[16];
        #pragma unroll
        for (int j = 0; j < 16; j++) {
            const int d = d0 + 2*j;
            float2 cc = *(const float2*)&ct[d];
            float2 ss = *(const float2*)&stb[d];
            float x1a = srow[d],      x1b = srow[d + 1];
            float x2a = srow[d + 64], x2b = srow[d + 65];
            float o1a = (x1a*cc.x - x2a*ss.x) * qs;
            float o1b = (x1b*cc.y - x2b*ss.y) * qs;
            float o2a = (x2a*cc.x + x1a*ss.x) * qs;
            float o2b = (x2b*cc.y + x1b*ss.y) * qs;
            split2(o1a, o1b, h1[j], l1[j]);
            split2(o2a, o2b, h2[j], l2[j]);
        }
        __nv_bfloat16* oh = (which == 0) ? g_qbh : g_kbh;
        __nv_bfloat16* ol = (which == 0) ? g_qbl : g_kbl;
        #pragma unroll
        for (int j = 0; j < 4; j++) {
            *(uint4*)&oh[obase + d0 + j*8]      = ((uint4*)h1)[j];
            *(uint4*)&ol[obase + d0 + j*8]      = ((uint4*)l1)[j];
            *(uint4*)&oh[obase + d0 + 64 + j*8] = ((uint4*)h2)[j];
            *(uint4*)&ol[obase + d0 + 64 + j*8] = ((uint4*)l2)[j];
        }
    }
}

// ---------------------------------------------------------------------------
// HMMA causal flash attention. BQ=128, BK=64, 8 warps (16 q-rows each).
// Double-buffered KV, ONE barrier per KV block (wait THEN sync).
// ---------------------------------------------------------------------------
__global__ __launch_bounds__(256, 1)
void attn_kernel()
{
    extern __shared__ char sm[];
    const uint32_t base = (smem_u32(sm) + 1023) & ~1023u;
    const uint32_t QH = base;                 // 2 panels x 16KB (dims 0-63, 64-127)
    const uint32_t QL = base + 32768;
    const uint32_t KV = base + 65536;         // buf b: +b*65536: Kh,Kl,Vh,Vl (16KB each)

    const int tid  = threadIdx.x;
    const int lane = tid & 31;
    const int wid  = tid >> 5;
    const int qt   = (int)gridDim.x - 1 - (int)blockIdx.x;  // heavy tiles first
    const int h    = blockIdx.y;
    const int b    = blockIdx.z;
    const int bh   = b*NHEAD + h;
    const int q0   = qt << 7;
    const int nkv  = 2*qt + 2;

    const size_t hoff = (size_t)bh * SEQ * HDIM;
    const __nv_bfloat16* qbh = g_qbh + hoff + (size_t)q0 * HDIM;
    const __nv_bfloat16* qbl = g_qbl + hoff + (size_t)q0 * HDIM;
    const __nv_bfloat16* kbh = g_kbh + hoff;
    const __nv_bfloat16* kbl = g_kbl + hoff;
    const __nv_bfloat16* vbh = g_vbh + hoff;
    const __nv_bfloat16* vbl = g_vbl + hoff;

    #pragma unroll
    for (int it = 0; it < 8; it++) {
        int i = tid + it * 256;
        int row = i >> 4, u = i & 15;
        uint32_t off = (u >> 3) * 16384 + SWZ(row * 128 + (u & 7) * 16);
        CP16(QH + off, qbh + (size_t)row * HDIM + u * 8);
        CP16(QL + off, qbl + (size_t)row * HDIM + u * 8);
    }
    {
        const __nv_bfloat16* arr[4] = {kbh, kbl, vbh, vbl};
        #pragma unroll
        for (int t = 0; t < 4; t++)
            #pragma unroll
            for (int it = 0; it < 4; it++) {
                int i = tid + it * 256;
                int row = i >> 4, u = i & 15;
                uint32_t d = KV + t*16384 + (u>>3)*8192 + SWZ(row*128 + (u&7)*16);
                CP16(d, arr[t] + (size_t)row * HDIM + u * 8);
            }
    }
    CP_COMMIT();
    CP_WAIT0();
    __syncthreads();

    float mr0 = -1e30f, mr1 = -1e30f, lr0 = 0.f, lr1 = 0.f;
    float o[16][4];
    #pragma unroll
    for (int t = 0; t < 16; t++)
        #pragma unroll
        for (int j = 0; j < 4; j++) o[t][j] = 0.f;

    const int rloc0 = wid*16 + (lane >> 2);
    const int rg0   = q0 + rloc0;

    for (int kt = 0; kt < nkv; kt++) {
        const uint32_t KB = KV + (kt & 1) * 65536;
        const uint32_t VB = KB + 32768;

        if (kt + 1 < nkv) {
            const __nv_bfloat16* arr[4] = {kbh, kbl, vbh, vbl};
            const size_t s0 = (size_t)(kt + 1) * 64 * HDIM;
            const uint32_t nb = KV + ((kt + 1) & 1) * 65536;
            #pragma unroll
            for (int t = 0; t < 4; t++)
                #pragma unroll
                for (int it = 0; it < 4; it++) {
                    int i = tid + it * 256;
                    int row = i >> 4, u = i & 15;
                    uint32_t d = nb + t*16384 + (u>>3)*8192 + SWZ(row*128 + (u&7)*16);
                    CP16(d, arr[t] + s0 + (size_t)row * HDIM + u * 8);
                }
            CP_COMMIT();
        }

        float s[8][4];
        #pragma unroll
        for (int t = 0; t < 8; t++)
            #pragma unroll
            for (int j = 0; j < 4; j++) s[t][j] = 0.f;

        #pragma unroll
        for (int ks = 0; ks < 8; ks++) {
            const int arow = wid*16 + (lane & 15);
            const uint32_t aoff = (ks>>2)*16384
                + SWZ(arow*128 + (ks&3)*32 + ((lane>>4)<<4));
            uint32_t qa[4], qla[4];
            ldsm4(QH + aoff, qa);
            ldsm4(QL + aoff, qla);

            const int krow0 = (lane & 7) + ((lane >> 4) << 3);
            const uint32_t kcol = (uint32_t)((ks&3)*32 + (((lane>>3)&1)<<4));
            #pragma unroll
            for (int ntp = 0; ntp < 4; ntp++) {
                const uint32_t koff = (ks>>2)*8192 + SWZ((ntp*16 + krow0)*128 + kcol);
                uint32_t kb4[4], klb4[4];
                ldsm4(KB + koff, kb4);
                ldsm4(KB + 16384 + koff, klb4);
                mma16816(s[2*ntp],   qa,  &kb4[0]);
                mma16816(s[2*ntp],   qa,  &klb4[0]);
                mma16816(s[2*ntp],   qla, &kb4[0]);
                mma16816(s[2*ntp+1], qa,  &kb4[2]);
                mma16816(s[2*ntp+1], qa,  &klb4[2]);
                mma16816(s[2*ntp+1], qla, &kb4[2]);
            }
        }

        if (kt >= 2*qt) {
            #pragma unroll
            for (int t = 0; t < 8; t++) {
                #pragma unroll
                for (int j = 0; j < 2; j++) {
                    const int n = kt*64 + t*8 + 2*(lane & 3) + j;
                    if (n > rg0)     s[t][j]   = -1e30f;
                    if (n > rg0 + 8) s[t][2+j] = -1e30f;
                }
            }
        }

        float rm0 = -1e30f, rm1 = -1e30f;
        #pragma unroll
        for (int t = 0; t < 8; t++) {
            rm0 = fmaxf(rm0, fmaxf(s[t][0], s[t][1]));
            rm1 = fmaxf(rm1, fmaxf(s[t][2], s[t][3]));
        }
        rm0 = fmaxf(rm0, __shfl_xor_sync(0xffffffffu, rm0, 1));
        rm0 = fmaxf(rm0, __shfl_xor_sync(0xffffffffu, rm0, 2));
        rm1 = fmaxf(rm1, __shfl_xor_sync(0xffffffffu, rm1, 1));
        rm1 = fmaxf(rm1, __shfl_xor_sync(0xffffffffu, rm1, 2));

        const float mn0 = fmaxf(mr0, rm0), mn1 = fmaxf(mr1, rm1);
        const float sf0 = __expf(mr0 - mn0), sf1 = __expf(mr1 - mn1);
        mr0 = mn0; mr1 = mn1;

        float rs0 = 0.f, rs1 = 0.f;
        #pragma unroll
        for (int t = 0; t < 8; t++) {
            s[t][0] = __expf(s[t][0] - mn0);
            s[t][1] = __expf(s[t][1] - mn0);
            s[t][2] = __expf(s[t][2] - mn1);
            s[t][3] = __expf(s[t][3] - mn1);
            rs0 += s[t][0] + s[t][1];
            rs1 += s[t][2] + s[t][3];
        }
        rs0 += __shfl_xor_sync(0xffffffffu, rs0, 1);
        rs0 += __shfl_xor_sync(0xffffffffu, rs0, 2);
        rs1 += __shfl_xor_sync(0xffffffffu, rs1, 1);
        rs1 += __shfl_xor_sync(0xffffffffu, rs1, 2);
        lr0 = lr0 * sf0 + rs0;
        lr1 = lr1 * sf1 + rs1;

        #pragma unroll
        for (int t = 0; t < 16; t++) {
            o[t][0] *= sf0; o[t][1] *= sf0;
            o[t][2] *= sf1; o[t][3] *= sf1;
        }

        uint32_t aph[4][4], apl[4][4];
        #pragma unroll
        for (int g = 0; g < 4; g++) {
            split2(s[2*g][0],   s[2*g][1],   aph[g][0], apl[g][0]);
            split2(s[2*g][2],   s[2*g][3],   aph[g][1], apl[g][1]);
            split2(s[2*g+1][0], s[2*g+1][1], aph[g][2], apl[g][2]);
            split2(s[2*g+1][2], s[2*g+1][3], aph[g][3], apl[g][3]);
        }

        const int vrow0 = (lane & 15);
        const uint32_t vcadd = (uint32_t)((lane >> 4) << 4);
        #pragma unroll
        for (int dtp = 0; dtp < 8; dtp++) {
            const uint32_t vcol = (uint32_t)((dtp&3)*32) + vcadd;
            #pragma unroll
            for (int g = 0; g < 4; g++) {
                const uint32_t voff = (dtp>>2)*8192 + SWZ((g*16 + vrow0)*128 + vcol);
                uint32_t vb4[4], vlb4[4];
                ldsm4t(VB + voff, vb4);
                ldsm4t(VB + 16384 + voff, vlb4);
                mma16816(o[2*dtp],   aph[g], &vb4[0]);
                mma16816(o[2*dtp],   aph[g], &vlb4[0]);
                mma16816(o[2*dtp],   apl[g], &vb4[0]);
                mma16816(o[2*dtp+1], aph[g], &vb4[2]);
                mma16816(o[2*dtp+1], aph[g], &vlb4[2]);
                mma16816(o[2*dtp+1], apl[g], &vb4[2]);
            }
        }

        if (kt + 1 < nkv) {
            CP_WAIT0();
            __syncthreads();
        }
    }

    const float inv0 = 1.f / lr0, inv1 = 1.f / lr1;
    const size_t row0 = ((size_t)(b*SEQ + rg0)) * D_MODEL + h*HDIM;
    const size_t row1 = row0 + 8 * D_MODEL;
    #pragma unroll
    for (int t = 0; t < 16; t++) {
        const int d = t*8 + 2*(lane & 3);
        uint32_t hi, lo;
        split2(o[t][0]*inv0, o[t][1]*inv0, hi, lo);
        *(uint32_t*)&g_ah[row0 + d] = hi;
        *(uint32_t*)&g_al[row0 + d] = lo;
        split2(o[t][2]*inv1, o[t][3]*inv1, hi, lo);
        *(uint32_t*)&g_ah[row1 + d] = hi;
        *(uint32_t*)&g_al[row1 + d] = lo;
    }
}

// ---------------------------------------------------------------------------
extern "C" void kernel_launch(void* const* d_in, const int* in_sizes, int n_in,
                              void* d_out, int out_size)
{
    const float* query = (const float*)d_in[0];
    const float* W_qkv = (const float*)d_in[1];
    const float* b_qkv = (const float*)d_in[2];
    const float* W_out = (const float*)d_in[3];
    const float* b_out = (const float*)d_in[4];
    float* out = (float*)d_out;

    void *p_qh, *p_ql, *p_wh, *p_wl, *p_oh, *p_ol, *p_ah, *p_al;
    cudaGetSymbolAddress(&p_qh, g_qh);  cudaGetSymbolAddress(&p_ql, g_ql);
    cudaGetSymbolAddress(&p_wh, g_wh);  cudaGetSymbolAddress(&p_wl, g_wl);
    cudaGetSymbolAddress(&p_oh, g_oh);  cudaGetSymbolAddress(&p_ol, g_ol);
    cudaGetSymbolAddress(&p_ah, g_ah);  cudaGetSymbolAddress(&p_al, g_al);

    const int GEMM_SMEM = 1024 + 3*32768;       // 3-stage K32 pipeline (2 CTAs/SM)
    cudaFuncSetAttribute(tc_gemm<0>, cudaFuncAttributeMaxDynamicSharedMemorySize, GEMM_SMEM);
    cudaFuncSetAttribute(tc_gemm<1>, cudaFuncAttributeMaxDynamicSharedMemorySize, GEMM_SMEM);
    const int ATTN_SMEM = 1024 + 65536 + 2*65536;
    cudaFuncSetAttribute(attn_kernel, cudaFuncAttributeMaxDynamicSharedMemorySize, ATTN_SMEM);

    // 0) rope tables (must precede QKV epilogue)
    rope_table_kernel<<<(SEQ*64)/256, 256>>>();

    // 1) split inputs into bf16 hi/lo
    {
        int n;
        n = MROWS*D_MODEL;
        split_kernel<<<n/1024, 256>>>(query, (__nv_bfloat16*)p_qh, (__nv_bfloat16*)p_ql, n);
        n = 3*D_MODEL*D_MODEL;
        split_kernel<<<n/1024, 256>>>(W_qkv, (__nv_bfloat16*)p_wh, (__nv_bfloat16*)p_wl, n);
        n = D_MODEL*D_MODEL;
        split_kernel<<<n/1024, 256>>>(W_out, (__nv_bfloat16*)p_oh, (__nv_bfloat16*)p_ol, n);
    }

    // 2) QKV projection (HMMA) with fused rope/split epilogue
    tc_gemm<1><<<dim3(3*D_MODEL/128, MROWS/128), 256, GEMM_SMEM>>>(
        (const __nv_bfloat16*)p_qh, (const __nv_bfloat16*)p_ql,
        (const __nv_bfloat16*)p_wh, (const __nv_bfloat16*)p_wl,
        b_qkv, nullptr, 3*D_MODEL, D_MODEL);

    // 3) HMMA causal flash attention -> g_ah/g_al
    attn_kernel<<<dim3(SEQ/128, NHEAD, BATCH), 256, ATTN_SMEM>>>();

    // 4) Output projection (HMMA) -> d_out
    tc_gemm<0><<<dim3(D_MODEL/128, MROWS/128), 256, GEMM_SMEM>>>(
        (const __nv_bfloat16*)p_ah, (const __nv_bfloat16*)p_al,
        (const __nv_bfloat16*)p_oh, (const __nv_bfloat16*)p_ol,
        b_out, out, D_MODEL, D_MODEL);
}